// round 1
// baseline (speedup 1.0000x reference)
#include <cuda_runtime.h>
#include <cuda_bf16.h>
#include <math.h>

// Problem constants
#define BATCH 16
#define CIN   256
#define HW    4096
#define O3    1536
#define HID   512
#define NH    8
#define HD    64
#define NMEM  4

// Scratch (device globals — allocation-free rule)
__device__ float g_s[BATCH * HW];              // 16 / max(||x_col||, 1e-12)
__device__ float g_wg[O3 * CIN];               // w_qkv * g_in[c]
__device__ float g_qkv[(size_t)BATCH * O3 * HW];   // 402 MB
__device__ float g_ctx[BATCH * NH * HD * HD];      // 2 MB
__device__ float g_att[(size_t)BATCH * HID * HW];  // 134 MB

// ---------------------------------------------------------------------------
// Kernel 1: per-position rmsnorm scale  s[b,pos] = 16 / max(||x[:,pos]||, eps)
// ---------------------------------------------------------------------------
__global__ __launch_bounds__(256) void colscale_kernel(const float* __restrict__ x,
                                                       float* __restrict__ s) {
    int idx = blockIdx.x * 256 + threadIdx.x;
    if (idx >= BATCH * HW) return;
    int b = idx >> 12, pos = idx & (HW - 1);
    const float* p = x + (size_t)b * CIN * HW + pos;
    float acc = 0.f;
#pragma unroll 8
    for (int c = 0; c < CIN; c++) {
        float v = p[(size_t)c * HW];
        acc += v * v;
    }
    s[idx] = 16.0f / fmaxf(sqrtf(acc), 1e-12f);
}

// ---------------------------------------------------------------------------
// Kernel 1b: fold g_in into w_qkv
// ---------------------------------------------------------------------------
__global__ __launch_bounds__(256) void wg_kernel(const float* __restrict__ w,
                                                 const float* __restrict__ g,
                                                 float* __restrict__ wg) {
    int i = blockIdx.x * 256 + threadIdx.x;
    if (i < O3 * CIN) wg[i] = w[i] * g[i & (CIN - 1)];
}

// ---------------------------------------------------------------------------
// Kernel 2: QKV GEMM per batch. C[1536,4096] = Wg[1536,256] @ X[256,4096],
// column-scaled by rmsnorm factor. 128x128x16 tile, 256 threads, 8x8/thread.
// ---------------------------------------------------------------------------
#define BM 128
#define BN 128
#define BK 16
__global__ __launch_bounds__(256) void qkv_gemm_kernel(const float* __restrict__ Wg,
                                                       const float* __restrict__ X,
                                                       const float* __restrict__ s,
                                                       float* __restrict__ out) {
    int b = blockIdx.z;
    const float* A  = Wg;                                   // [1536][256]
    const float* Bx = X + (size_t)b * CIN * HW;             // [256][4096]
    float* C = out + (size_t)b * O3 * HW;

    __shared__ float As[BK][BM];
    __shared__ float Bs[BK][BN];

    int tid = threadIdx.x;
    int tx = tid & 15, ty = tid >> 4;
    int rowBase = blockIdx.y * BM;
    int colBase = blockIdx.x * BN;

    float acc[8][8];
#pragma unroll
    for (int i = 0; i < 8; i++)
#pragma unroll
        for (int j = 0; j < 8; j++) acc[i][j] = 0.f;

    for (int k0 = 0; k0 < CIN; k0 += BK) {
        // Load A tile 128x16 (transposed into As[k][m])
#pragma unroll
        for (int l = 0; l < 2; l++) {
            int lin = tid + l * 256;
            int r = lin >> 2, kq = lin & 3;
            float4 a = *(const float4*)(A + (size_t)(rowBase + r) * CIN + k0 + kq * 4);
            As[kq * 4 + 0][r] = a.x;
            As[kq * 4 + 1][r] = a.y;
            As[kq * 4 + 2][r] = a.z;
            As[kq * 4 + 3][r] = a.w;
        }
        // Load B tile 16x128
#pragma unroll
        for (int l = 0; l < 2; l++) {
            int lin = tid + l * 256;
            int kr = lin >> 5, cq = lin & 31;
            *(float4*)(&Bs[kr][cq * 4]) =
                *(const float4*)(Bx + (size_t)(k0 + kr) * HW + colBase + cq * 4);
        }
        __syncthreads();
#pragma unroll
        for (int kk = 0; kk < BK; kk++) {
            float af[8], bf[8];
            *(float4*)(af)     = *(const float4*)(&As[kk][ty * 8]);
            *(float4*)(af + 4) = *(const float4*)(&As[kk][ty * 8 + 4]);
            *(float4*)(bf)     = *(const float4*)(&Bs[kk][tx * 8]);
            *(float4*)(bf + 4) = *(const float4*)(&Bs[kk][tx * 8 + 4]);
#pragma unroll
            for (int i = 0; i < 8; i++)
#pragma unroll
                for (int j = 0; j < 8; j++) acc[i][j] += af[i] * bf[j];
        }
        __syncthreads();
    }

    const float* sb = s + b * HW;
    float scv[8];
#pragma unroll
    for (int j = 0; j < 8; j++) scv[j] = sb[colBase + tx * 8 + j];
#pragma unroll
    for (int i = 0; i < 8; i++) {
        size_t ro = (size_t)(rowBase + ty * 8 + i) * HW + colBase + tx * 8;
        float4 v0 = make_float4(acc[i][0] * scv[0], acc[i][1] * scv[1],
                                acc[i][2] * scv[2], acc[i][3] * scv[3]);
        float4 v1 = make_float4(acc[i][4] * scv[4], acc[i][5] * scv[5],
                                acc[i][6] * scv[6], acc[i][7] * scv[7]);
        *(float4*)(C + ro)     = v0;
        *(float4*)(C + ro + 4) = v1;
    }
}

// ---------------------------------------------------------------------------
// Kernel 3: per (b,h): k-softmax over n (4096 spatial + 4 mem) and
// context[d][e] = sum_n ksoft[d][n] * v[e][n]
// ---------------------------------------------------------------------------
__global__ __launch_bounds__(256) void context_kernel(const float* __restrict__ qkv,
                                                      const float* __restrict__ memkv,
                                                      float* __restrict__ ctx) {
    int h = blockIdx.x, b = blockIdx.y;
    const float* K = qkv + ((size_t)b * O3 + HID + h * HD) * HW;
    const float* V = qkv + ((size_t)b * O3 + 2 * HID + h * HD) * HW;
    const float* MK = memkv + (size_t)h * HD * NMEM;
    const float* MV = memkv + (size_t)NH * HD * NMEM + (size_t)h * HD * NMEM;

    __shared__ float rmax[HD], rinv[HD];
    __shared__ float Ks[HD][65];
    __shared__ float Vs[HD][65];

    int tid = threadIdx.x;
    int lane = tid & 31, warp = tid >> 5;

    // Pass 1: row max & sum(exp) over 4100 entries; warp w handles rows w*8..w*8+7
    for (int r = 0; r < 8; r++) {
        int d = warp * 8 + r;
        const float* kr = K + (size_t)d * HW;
        float m = -1e30f;
        for (int n = lane; n < HW; n += 32) m = fmaxf(m, kr[n]);
        if (lane < NMEM) m = fmaxf(m, MK[d * NMEM + lane]);
#pragma unroll
        for (int o = 16; o; o >>= 1) m = fmaxf(m, __shfl_xor_sync(0xFFFFFFFFu, m, o));
        float ss = 0.f;
        for (int n = lane; n < HW; n += 32) ss += __expf(kr[n] - m);
        if (lane < NMEM) ss += __expf(MK[d * NMEM + lane] - m);
#pragma unroll
        for (int o = 16; o; o >>= 1) ss += __shfl_xor_sync(0xFFFFFFFFu, ss, o);
        if (lane == 0) { rmax[d] = m; rinv[d] = 1.0f / ss; }
    }
    __syncthreads();

    int tx = tid & 15, ty = tid >> 4;
    float acc[4][4];
#pragma unroll
    for (int i = 0; i < 4; i++)
#pragma unroll
        for (int j = 0; j < 4; j++) acc[i][j] = 0.f;

    for (int n0 = 0; n0 < HW; n0 += 64) {
#pragma unroll
        for (int l = 0; l < 16; l++) {
            int lin = l * 256 + tid;
            int d = lin >> 6, j = lin & 63;
            float kv = K[(size_t)d * HW + n0 + j];
            Ks[d][j] = __expf(kv - rmax[d]) * rinv[d];
            Vs[d][j] = V[(size_t)d * HW + n0 + j];
        }
        __syncthreads();
#pragma unroll 8
        for (int j = 0; j < 64; j++) {
            float kf[4], vf[4];
#pragma unroll
            for (int i = 0; i < 4; i++) kf[i] = Ks[ty * 4 + i][j];
#pragma unroll
            for (int i = 0; i < 4; i++) vf[i] = Vs[tx * 4 + i][j];
#pragma unroll
            for (int i = 0; i < 4; i++)
#pragma unroll
                for (int ii = 0; ii < 4; ii++) acc[i][ii] += kf[i] * vf[ii];
        }
        __syncthreads();
    }

    // Memory-KV tail (4 columns)
#pragma unroll
    for (int j = 0; j < NMEM; j++) {
        float kf[4], vf[4];
#pragma unroll
        for (int i = 0; i < 4; i++) {
            int d = ty * 4 + i;
            kf[i] = __expf(MK[d * NMEM + j] - rmax[d]) * rinv[d];
        }
#pragma unroll
        for (int ii = 0; ii < 4; ii++) vf[ii] = MV[(tx * 4 + ii) * NMEM + j];
#pragma unroll
        for (int i = 0; i < 4; i++)
#pragma unroll
            for (int ii = 0; ii < 4; ii++) acc[i][ii] += kf[i] * vf[ii];
    }

    float* cb = ctx + (size_t)(b * NH + h) * HD * HD;
#pragma unroll
    for (int i = 0; i < 4; i++)
#pragma unroll
        for (int ii = 0; ii < 4; ii++)
            cb[(size_t)(ty * 4 + i) * HD + tx * 4 + ii] = acc[i][ii];
}

// ---------------------------------------------------------------------------
// Kernel 4: per (b,h,64-pos tile): q-softmax over d, out[e][p] = sum_d ctx[d][e]*qs[d][p]
// ---------------------------------------------------------------------------
__global__ __launch_bounds__(256) void attend_kernel(const float* __restrict__ qkv,
                                                     const float* __restrict__ ctx,
                                                     float* __restrict__ att) {
    int pos0 = blockIdx.x * 64;
    int h = blockIdx.y, b = blockIdx.z;
    const float* Q = qkv + ((size_t)b * O3 + h * HD) * HW;
    const float* cb = ctx + (size_t)(b * NH + h) * HD * HD;

    __shared__ float qs[HD][68];
    __shared__ float cs[HD][68];

    int tid = threadIdx.x;

    // ctx into smem (all threads)
    for (int l = tid; l < HD * HD; l += 256)
        cs[l >> 6][l & 63] = cb[l];

    // q softmax: threads 0..63, one position each
    if (tid < 64) {
        const float* qp = Q + pos0 + tid;
        float m = -1e30f;
#pragma unroll 8
        for (int d = 0; d < HD; d++) m = fmaxf(m, qp[(size_t)d * HW]);
        float ss = 0.f;
#pragma unroll 8
        for (int d = 0; d < HD; d++) ss += __expf(qp[(size_t)d * HW] - m);
        float inv = 0.125f / ss;  // * HEAD_DIM^-0.5
#pragma unroll 8
        for (int d = 0; d < HD; d++)
            qs[d][tid] = __expf(qp[(size_t)d * HW] - m) * inv;
    }
    __syncthreads();

    // GEMM: out[e][p] = sum_d cs[d][e] * qs[d][p]; 16x16 threads, 4x4 tile
    int tx = tid & 15, ty = tid >> 4;
    float acc[4][4];
#pragma unroll
    for (int i = 0; i < 4; i++)
#pragma unroll
        for (int j = 0; j < 4; j++) acc[i][j] = 0.f;

#pragma unroll 8
    for (int d = 0; d < HD; d++) {
        float4 cf = *(const float4*)(&cs[d][ty * 4]);
        float4 qf = *(const float4*)(&qs[d][tx * 4]);
        float cfa[4] = {cf.x, cf.y, cf.z, cf.w};
        float qfa[4] = {qf.x, qf.y, qf.z, qf.w};
#pragma unroll
        for (int i = 0; i < 4; i++)
#pragma unroll
            for (int j = 0; j < 4; j++) acc[i][j] += cfa[i] * qfa[j];
    }

    float* ob = att + ((size_t)b * HID + h * HD) * HW + pos0;
#pragma unroll
    for (int i = 0; i < 4; i++) {
        int e = ty * 4 + i;
        *(float4*)(ob + (size_t)e * HW + tx * 4) =
            make_float4(acc[i][0], acc[i][1], acc[i][2], acc[i][3]);
    }
}

// ---------------------------------------------------------------------------
// Kernel 5: out GEMM [256,512]@[512,32-pos-tile] + bias + fused rmsnorm
// Block covers ALL 256 output channels so rmsnorm can fuse.
// ---------------------------------------------------------------------------
__global__ __launch_bounds__(256) void outnorm_kernel(const float* __restrict__ Wo,
                                                      const float* __restrict__ att,
                                                      const float* __restrict__ bias,
                                                      const float* __restrict__ gout,
                                                      float* __restrict__ out) {
    int b = blockIdx.y;
    int pos0 = blockIdx.x * 32;
    const float* Ab = att + (size_t)b * HID * HW;

    __shared__ float Ws[16][256];
    __shared__ float As[16][32];
    __shared__ float csum[32];

    int tid = threadIdx.x;
    int tx = tid & 7, ty = tid >> 3;     // ty: 0..31 row groups of 8, tx: 0..7 col groups of 4

    float acc[8][4];
#pragma unroll
    for (int i = 0; i < 8; i++)
#pragma unroll
        for (int j = 0; j < 4; j++) acc[i][j] = 0.f;

    for (int k0 = 0; k0 < HID; k0 += 16) {
        // W tile: 256 rows x 16 k, transposed into Ws[k][row]
#pragma unroll
        for (int l = 0; l < 4; l++) {
            int lin = tid + l * 256;
            int r = lin >> 2, kq = lin & 3;
            float4 w = *(const float4*)(Wo + (size_t)r * HID + k0 + kq * 4);
            Ws[kq * 4 + 0][r] = w.x;
            Ws[kq * 4 + 1][r] = w.y;
            Ws[kq * 4 + 2][r] = w.z;
            Ws[kq * 4 + 3][r] = w.w;
        }
        // A tile: 16 k x 32 cols
#pragma unroll
        for (int l = 0; l < 2; l++) {
            int lin = tid + l * 256;
            int kr = lin >> 5, c = lin & 31;
            As[kr][c] = Ab[(size_t)(k0 + kr) * HW + pos0 + c];
        }
        __syncthreads();
#pragma unroll
        for (int kk = 0; kk < 16; kk++) {
            float wf[8], af[4];
            *(float4*)(wf)     = *(const float4*)(&Ws[kk][ty * 8]);
            *(float4*)(wf + 4) = *(const float4*)(&Ws[kk][ty * 8 + 4]);
            *(float4*)(af)     = *(const float4*)(&As[kk][tx * 4]);
#pragma unroll
            for (int i = 0; i < 8; i++)
#pragma unroll
                for (int j = 0; j < 4; j++) acc[i][j] += wf[i] * af[j];
        }
        __syncthreads();
    }

    // add bias
#pragma unroll
    for (int i = 0; i < 8; i++) {
        float bi = bias[ty * 8 + i];
#pragma unroll
        for (int j = 0; j < 4; j++) acc[i][j] += bi;
    }

    // column sum of squares over all 256 rows
    if (tid < 32) csum[tid] = 0.f;
    __syncthreads();
#pragma unroll
    for (int j = 0; j < 4; j++) {
        float p = 0.f;
#pragma unroll
        for (int i = 0; i < 8; i++) p += acc[i][j] * acc[i][j];
        atomicAdd(&csum[tx * 4 + j], p);
    }
    __syncthreads();

    float inv[4];
#pragma unroll
    for (int j = 0; j < 4; j++)
        inv[j] = 16.0f / fmaxf(sqrtf(csum[tx * 4 + j]), 1e-12f);

    float* ob = out + (size_t)b * CIN * HW + pos0;
#pragma unroll
    for (int i = 0; i < 8; i++) {
        int row = ty * 8 + i;
        float gr = gout[row];
        float4 v = make_float4(acc[i][0] * inv[0] * gr, acc[i][1] * inv[1] * gr,
                               acc[i][2] * inv[2] * gr, acc[i][3] * inv[3] * gr);
        *(float4*)(ob + (size_t)row * HW + tx * 4) = v;
    }
}

// ---------------------------------------------------------------------------
extern "C" void kernel_launch(void* const* d_in, const int* in_sizes, int n_in,
                              void* d_out, int out_size) {
    const float* x      = (const float*)d_in[0];   // [16,256,64,64]
    const float* g_in   = (const float*)d_in[1];   // [256]
    const float* w_qkv  = (const float*)d_in[2];   // [1536,256]
    const float* mem_kv = (const float*)d_in[3];   // [2,8,64,4]
    const float* w_out  = (const float*)d_in[4];   // [256,512]
    const float* b_out  = (const float*)d_in[5];   // [256]
    const float* g_out  = (const float*)d_in[6];   // [256]
    float* out = (float*)d_out;

    float *s_ptr, *wg_ptr, *qkv_ptr, *ctx_ptr, *att_ptr;
    cudaGetSymbolAddress((void**)&s_ptr,   g_s);
    cudaGetSymbolAddress((void**)&wg_ptr,  g_wg);
    cudaGetSymbolAddress((void**)&qkv_ptr, g_qkv);
    cudaGetSymbolAddress((void**)&ctx_ptr, g_ctx);
    cudaGetSymbolAddress((void**)&att_ptr, g_att);

    colscale_kernel<<<(BATCH * HW + 255) / 256, 256>>>(x, s_ptr);
    wg_kernel<<<(O3 * CIN + 255) / 256, 256>>>(w_qkv, g_in, wg_ptr);
    qkv_gemm_kernel<<<dim3(HW / BN, O3 / BM, BATCH), 256>>>(wg_ptr, x, s_ptr, qkv_ptr);
    context_kernel<<<dim3(NH, BATCH), 256>>>(qkv_ptr, mem_kv, ctx_ptr);
    attend_kernel<<<dim3(HW / 64, NH, BATCH), 256>>>(qkv_ptr, ctx_ptr, att_ptr);
    outnorm_kernel<<<dim3(HW / 32, BATCH), 256>>>(w_out, att_ptr, b_out, g_out, out);
}

// round 2
// speedup vs baseline: 1.1970x; 1.1970x over previous
#include <cuda_runtime.h>
#include <math.h>

// Problem constants
#define BATCH 16
#define CIN   256
#define HW    4096
#define O3    1536
#define HID   512
#define NH    8
#define HD    64
#define NMEM  4
#define NC    8
#define CHUNK 512

typedef unsigned long long u64;

// Scratch (device globals — allocation-free rule)
__device__ float g_s[BATCH * HW];
__device__ float g_wg[O3 * CIN];
__device__ float g_qkv[(size_t)BATCH * O3 * HW];          // 402 MB
__device__ float g_rmax[BATCH * NH * HD];
__device__ float g_rinv[BATCH * NH * HD];
__device__ float g_part[(size_t)NC * BATCH * NH * HD * HD]; // 16.8 MB
__device__ float g_ctx[BATCH * NH * HD * HD];
__device__ float g_att[(size_t)BATCH * HID * HW];         // 134 MB

// ---- packed f32x2 helpers (FFMA2: 2x fp32 FMA throughput, PTX-only) ------
__device__ __forceinline__ u64 pack_dup(float v) {
    u64 r; asm("mov.b64 %0, {%1, %2};" : "=l"(r) : "f"(v), "f"(v)); return r;
}
__device__ __forceinline__ void ffma2(u64& d, u64 a, u64 b) {
    asm("fma.rn.f32x2 %0, %1, %2, %0;" : "+l"(d) : "l"(a), "l"(b));
}
__device__ __forceinline__ float2 unpack2(u64 v) {
    float2 f; asm("mov.b64 {%0, %1}, %2;" : "=f"(f.x), "=f"(f.y) : "l"(v)); return f;
}

// ---------------------------------------------------------------------------
// Kernel 1: per-position rmsnorm scale  s[b,pos] = 16 / max(||x[:,pos]||, eps)
// ---------------------------------------------------------------------------
__global__ __launch_bounds__(256) void colscale_kernel(const float* __restrict__ x,
                                                       float* __restrict__ s) {
    int idx = blockIdx.x * 256 + threadIdx.x;
    if (idx >= BATCH * HW) return;
    int b = idx >> 12, pos = idx & (HW - 1);
    const float* p = x + (size_t)b * CIN * HW + pos;
    float acc = 0.f;
#pragma unroll 8
    for (int c = 0; c < CIN; c++) {
        float v = p[(size_t)c * HW];
        acc += v * v;
    }
    s[idx] = 16.0f / fmaxf(sqrtf(acc), 1e-12f);
}

// ---------------------------------------------------------------------------
// Kernel 1b: fold g_in into w_qkv
// ---------------------------------------------------------------------------
__global__ __launch_bounds__(256) void wg_kernel(const float* __restrict__ w,
                                                 const float* __restrict__ g,
                                                 float* __restrict__ wg) {
    int i = blockIdx.x * 256 + threadIdx.x;
    if (i < O3 * CIN) wg[i] = w[i] * g[i & (CIN - 1)];
}

// ---------------------------------------------------------------------------
// Kernel 2: QKV GEMM per batch. C[1536,4096] = Wg[1536,256] @ X[256,4096],
// column-scaled. 128x128x16 tile, 256 threads, 8x8/thread via f32x2 FMA.
// ---------------------------------------------------------------------------
#define BM 128
#define BN 128
#define BK 16
__global__ __launch_bounds__(256) void qkv_gemm_kernel(const float* __restrict__ Wg,
                                                       const float* __restrict__ X,
                                                       const float* __restrict__ s,
                                                       float* __restrict__ out) {
    int b = blockIdx.z;
    const float* A  = Wg;
    const float* Bx = X + (size_t)b * CIN * HW;
    float* C = out + (size_t)b * O3 * HW;

    __shared__ __align__(16) float As[BK][BM];
    __shared__ __align__(16) float Bs[BK][BN];

    int tid = threadIdx.x;
    int tx = tid & 15, ty = tid >> 4;
    int rowBase = blockIdx.y * BM;
    int colBase = blockIdx.x * BN;

    u64 acc[8][4];
#pragma unroll
    for (int i = 0; i < 8; i++)
#pragma unroll
        for (int j = 0; j < 4; j++) acc[i][j] = 0ULL;

    for (int k0 = 0; k0 < CIN; k0 += BK) {
#pragma unroll
        for (int l = 0; l < 2; l++) {
            int lin = tid + l * 256;
            int r = lin >> 2, kq = lin & 3;
            float4 a = *(const float4*)(A + (size_t)(rowBase + r) * CIN + k0 + kq * 4);
            As[kq * 4 + 0][r] = a.x;
            As[kq * 4 + 1][r] = a.y;
            As[kq * 4 + 2][r] = a.z;
            As[kq * 4 + 3][r] = a.w;
        }
#pragma unroll
        for (int l = 0; l < 2; l++) {
            int lin = tid + l * 256;
            int kr = lin >> 5, cq = lin & 31;
            *(float4*)(&Bs[kr][cq * 4]) =
                *(const float4*)(Bx + (size_t)(k0 + kr) * HW + colBase + cq * 4);
        }
        __syncthreads();
#pragma unroll
        for (int kk = 0; kk < BK; kk++) {
            float af[8];
            *(float4*)(af)     = *(const float4*)(&As[kk][ty * 8]);
            *(float4*)(af + 4) = *(const float4*)(&As[kk][ty * 8 + 4]);
            u64 aa[8];
#pragma unroll
            for (int i = 0; i < 8; i++) aa[i] = pack_dup(af[i]);
            ulonglong2 b0 = *(const ulonglong2*)(&Bs[kk][tx * 8]);
            ulonglong2 b1 = *(const ulonglong2*)(&Bs[kk][tx * 8 + 4]);
            u64 bb[4] = {b0.x, b0.y, b1.x, b1.y};
#pragma unroll
            for (int i = 0; i < 8; i++)
#pragma unroll
                for (int j = 0; j < 4; j++) ffma2(acc[i][j], aa[i], bb[j]);
        }
        __syncthreads();
    }

    const float* sb = s + b * HW;
    float scv[8];
#pragma unroll
    for (int j = 0; j < 8; j++) scv[j] = sb[colBase + tx * 8 + j];
#pragma unroll
    for (int i = 0; i < 8; i++) {
        float2 p0 = unpack2(acc[i][0]);
        float2 p1 = unpack2(acc[i][1]);
        float2 p2 = unpack2(acc[i][2]);
        float2 p3 = unpack2(acc[i][3]);
        size_t ro = (size_t)(rowBase + ty * 8 + i) * HW + colBase + tx * 8;
        *(float4*)(C + ro) =
            make_float4(p0.x * scv[0], p0.y * scv[1], p1.x * scv[2], p1.y * scv[3]);
        *(float4*)(C + ro + 4) =
            make_float4(p2.x * scv[4], p2.y * scv[5], p3.x * scv[6], p3.y * scv[7]);
    }
}

// ---------------------------------------------------------------------------
// Kernel 3a: k-softmax stats per (b,h,d) row: rmax, rinv over 4096+4 entries.
// One block per row; one global read; block reduce.
// ---------------------------------------------------------------------------
__global__ __launch_bounds__(256) void kstats_kernel(const float* __restrict__ qkv,
                                                     const float* __restrict__ memkv,
                                                     float* __restrict__ rmax,
                                                     float* __restrict__ rinv) {
    int d = blockIdx.x, h = blockIdx.y, b = blockIdx.z;
    int tid = threadIdx.x;
    const float* kr = qkv + ((size_t)b * O3 + HID + h * HD + d) * HW;
    const float* MK = memkv + ((size_t)h * HD + d) * NMEM;

    float v[16];
#pragma unroll
    for (int i = 0; i < 16; i++) v[i] = kr[i * 256 + tid];
    float m = v[0];
#pragma unroll
    for (int i = 1; i < 16; i++) m = fmaxf(m, v[i]);
    if (tid < NMEM) m = fmaxf(m, MK[tid]);

    __shared__ float red[8];
#pragma unroll
    for (int o = 16; o; o >>= 1) m = fmaxf(m, __shfl_xor_sync(0xFFFFFFFFu, m, o));
    if ((tid & 31) == 0) red[tid >> 5] = m;
    __syncthreads();
    if (tid == 0) {
        float t = red[0];
#pragma unroll
        for (int i = 1; i < 8; i++) t = fmaxf(t, red[i]);
        red[0] = t;
    }
    __syncthreads();
    m = red[0];
    __syncthreads();

    float ss = 0.f;
#pragma unroll
    for (int i = 0; i < 16; i++) ss += __expf(v[i] - m);
    if (tid < NMEM) ss += __expf(MK[tid] - m);
#pragma unroll
    for (int o = 16; o; o >>= 1) ss += __shfl_xor_sync(0xFFFFFFFFu, ss, o);
    if ((tid & 31) == 0) red[tid >> 5] = ss;
    __syncthreads();
    if (tid == 0) {
        float t = 0.f;
#pragma unroll
        for (int i = 0; i < 8; i++) t += red[i];
        int idx = (b * NH + h) * HD + d;
        rmax[idx] = m;
        rinv[idx] = 1.0f / t;
    }
}

// ---------------------------------------------------------------------------
// Kernel 3b: partial context over n chunks. part[c][b,h][d][e] =
//   sum_{n in chunk c} exp(K[d][n]-rmax[d]) * V[e][n]
// grid (NC, NH, BATCH); 256 thr, 4x4/thread via f32x2.
// ---------------------------------------------------------------------------
__global__ __launch_bounds__(256) void ctxpart_kernel(const float* __restrict__ qkv,
                                                      const float* __restrict__ rmax,
                                                      float* __restrict__ part) {
    int c = blockIdx.x, h = blockIdx.y, b = blockIdx.z;
    const float* K = qkv + ((size_t)b * O3 + HID + h * HD) * HW;
    const float* V = qkv + ((size_t)b * O3 + 2 * HID + h * HD) * HW;

    __shared__ __align__(16) float Kt[64][68];  // [n][d]
    __shared__ __align__(16) float Vt[64][68];  // [n][e]
    __shared__ float rm[64];

    int tid = threadIdx.x;
    if (tid < 64) rm[tid] = rmax[(b * NH + h) * HD + tid];
    __syncthreads();

    int tx = tid & 15, ty = tid >> 4;
    u64 acc[4][2];
#pragma unroll
    for (int i = 0; i < 4; i++) { acc[i][0] = 0ULL; acc[i][1] = 0ULL; }

    for (int nt = 0; nt < CHUNK / 64; nt++) {
        int n0 = c * CHUNK + nt * 64;
#pragma unroll
        for (int l = 0; l < 16; l++) {
            int lin = l * 256 + tid;
            int d = lin >> 6, j = lin & 63;
            Kt[j][d] = __expf(K[(size_t)d * HW + n0 + j] - rm[d]);
            Vt[j][d] = V[(size_t)d * HW + n0 + j];
        }
        __syncthreads();
#pragma unroll 4
        for (int j = 0; j < 64; j++) {
            float4 kf = *(const float4*)(&Kt[j][ty * 4]);
            u64 k0 = pack_dup(kf.x), k1 = pack_dup(kf.y);
            u64 k2 = pack_dup(kf.z), k3 = pack_dup(kf.w);
            ulonglong2 vv = *(const ulonglong2*)(&Vt[j][tx * 4]);
            ffma2(acc[0][0], k0, vv.x); ffma2(acc[0][1], k0, vv.y);
            ffma2(acc[1][0], k1, vv.x); ffma2(acc[1][1], k1, vv.y);
            ffma2(acc[2][0], k2, vv.x); ffma2(acc[2][1], k2, vv.y);
            ffma2(acc[3][0], k3, vv.x); ffma2(acc[3][1], k3, vv.y);
        }
        __syncthreads();
    }

    float* pb = part + ((size_t)c * BATCH * NH + b * NH + h) * (HD * HD);
#pragma unroll
    for (int i = 0; i < 4; i++) {
        float2 a = unpack2(acc[i][0]);
        float2 bb = unpack2(acc[i][1]);
        *(float4*)(&pb[(ty * 4 + i) * HD + tx * 4]) = make_float4(a.x, a.y, bb.x, bb.y);
    }
}

// ---------------------------------------------------------------------------
// Kernel 3c: reduce partials + mem-kv tail + rinv scaling -> ctx
// ---------------------------------------------------------------------------
__global__ __launch_bounds__(256) void ctxreduce_kernel(const float* __restrict__ part,
                                                        const float* __restrict__ memkv,
                                                        const float* __restrict__ rmax,
                                                        const float* __restrict__ rinv,
                                                        float* __restrict__ ctx) {
    int h = blockIdx.x, b = blockIdx.y;
    __shared__ float mkx[64][4];
    __shared__ float mvs[64][4];
    __shared__ float riv[64];
    int tid = threadIdx.x;
    if (tid < 64) riv[tid] = rinv[(b * NH + h) * HD + tid];
    {
        int d = tid >> 2, j = tid & 3;
        mkx[d][j] = __expf(memkv[((size_t)h * HD + d) * NMEM + j] -
                           rmax[(b * NH + h) * HD + d]);
        mvs[d][j] = memkv[(size_t)NH * HD * NMEM + ((size_t)h * HD + d) * NMEM + j];
    }
    __syncthreads();
    size_t base = (size_t)(b * NH + h) * (HD * HD);
    for (int l = tid; l < HD * HD; l += 256) {
        int d = l >> 6, e = l & 63;
        float s2 = 0.f;
#pragma unroll
        for (int cc = 0; cc < NC; cc++)
            s2 += part[(size_t)cc * BATCH * NH * HD * HD + base + l];
#pragma unroll
        for (int j = 0; j < 4; j++) s2 += mkx[d][j] * mvs[e][j];
        ctx[base + l] = s2 * riv[d];
    }
}

// ---------------------------------------------------------------------------
// Kernel 4: q-softmax over d + out[e][p] = sum_d ctx[d][e]*qs[d][p]
// ---------------------------------------------------------------------------
__global__ __launch_bounds__(256) void attend_kernel(const float* __restrict__ qkv,
                                                     const float* __restrict__ ctx,
                                                     float* __restrict__ att) {
    int pos0 = blockIdx.x * 64;
    int h = blockIdx.y, b = blockIdx.z;
    const float* Q = qkv + ((size_t)b * O3 + h * HD) * HW;
    const float* cb = ctx + (size_t)(b * NH + h) * HD * HD;

    __shared__ __align__(16) float cs[64][68];
    __shared__ __align__(16) float qs[64][68];

    int tid = threadIdx.x;
    for (int l = tid; l < HD * HD; l += 256) {
        int d = l >> 6, e = l & 63;
        cs[d][e] = cb[l];
        qs[d][e] = Q[(size_t)d * HW + pos0 + e];
    }
    __syncthreads();

    if (tid < 64) {
        float m = -1e30f;
#pragma unroll
        for (int d = 0; d < HD; d++) m = fmaxf(m, qs[d][tid]);
        float ss = 0.f;
#pragma unroll
        for (int d = 0; d < HD; d++) ss += __expf(qs[d][tid] - m);
        float inv = 0.125f / ss;  // * HEAD_DIM^-0.5
#pragma unroll
        for (int d = 0; d < HD; d++)
            qs[d][tid] = __expf(qs[d][tid] - m) * inv;
    }
    __syncthreads();

    int tx = tid & 15, ty = tid >> 4;
    u64 acc[4][2];
#pragma unroll
    for (int i = 0; i < 4; i++) { acc[i][0] = 0ULL; acc[i][1] = 0ULL; }

#pragma unroll 4
    for (int d = 0; d < HD; d++) {
        float4 cf = *(const float4*)(&cs[d][ty * 4]);
        u64 c0 = pack_dup(cf.x), c1 = pack_dup(cf.y);
        u64 c2 = pack_dup(cf.z), c3 = pack_dup(cf.w);
        ulonglong2 qq = *(const ulonglong2*)(&qs[d][tx * 4]);
        ffma2(acc[0][0], c0, qq.x); ffma2(acc[0][1], c0, qq.y);
        ffma2(acc[1][0], c1, qq.x); ffma2(acc[1][1], c1, qq.y);
        ffma2(acc[2][0], c2, qq.x); ffma2(acc[2][1], c2, qq.y);
        ffma2(acc[3][0], c3, qq.x); ffma2(acc[3][1], c3, qq.y);
    }

    float* ob = att + ((size_t)b * HID + h * HD) * HW + pos0;
#pragma unroll
    for (int i = 0; i < 4; i++) {
        float2 a = unpack2(acc[i][0]);
        float2 bb = unpack2(acc[i][1]);
        *(float4*)(ob + (size_t)(ty * 4 + i) * HW + tx * 4) =
            make_float4(a.x, a.y, bb.x, bb.y);
    }
}

// ---------------------------------------------------------------------------
// Kernel 5: out GEMM [256,512]@[512,64-pos-tile] + bias + fused rmsnorm.
// Block covers ALL 256 output channels so rmsnorm fuses. f32x2 FMAs.
// ---------------------------------------------------------------------------
__global__ __launch_bounds__(256) void outnorm_kernel(const float* __restrict__ Wo,
                                                      const float* __restrict__ att,
                                                      const float* __restrict__ bias,
                                                      const float* __restrict__ gout,
                                                      float* __restrict__ out) {
    int b = blockIdx.y;
    int pos0 = blockIdx.x * 64;
    const float* Ab = att + (size_t)b * HID * HW;

    __shared__ __align__(16) float Ws[16][256];
    __shared__ __align__(16) float As[16][64];
    __shared__ float psum[32][65];
    __shared__ float invs[64];

    int tid = threadIdx.x;
    int tx = tid & 7, ty = tid >> 3;  // ty: 32 row-groups of 8; tx: 8 col-groups of 8

    u64 acc[8][4];
#pragma unroll
    for (int i = 0; i < 8; i++)
#pragma unroll
        for (int j = 0; j < 4; j++) acc[i][j] = 0ULL;

    for (int k0 = 0; k0 < HID; k0 += 16) {
#pragma unroll
        for (int l = 0; l < 4; l++) {
            int lin = tid + l * 256;
            int r = lin >> 2, kq = lin & 3;
            float4 w = *(const float4*)(Wo + (size_t)r * HID + k0 + kq * 4);
            Ws[kq * 4 + 0][r] = w.x;
            Ws[kq * 4 + 1][r] = w.y;
            Ws[kq * 4 + 2][r] = w.z;
            Ws[kq * 4 + 3][r] = w.w;
        }
        {
            int kr = tid >> 4, cc = (tid & 15) * 4;
            *(float4*)(&As[kr][cc]) =
                *(const float4*)(Ab + (size_t)(k0 + kr) * HW + pos0 + cc);
        }
        __syncthreads();
#pragma unroll
        for (int kk = 0; kk < 16; kk++) {
            float wf[8];
            *(float4*)(wf)     = *(const float4*)(&Ws[kk][ty * 8]);
            *(float4*)(wf + 4) = *(const float4*)(&Ws[kk][ty * 8 + 4]);
            u64 wa[8];
#pragma unroll
            for (int i = 0; i < 8; i++) wa[i] = pack_dup(wf[i]);
            ulonglong2 a0 = *(const ulonglong2*)(&As[kk][tx * 8]);
            ulonglong2 a1 = *(const ulonglong2*)(&As[kk][tx * 8 + 4]);
            u64 av[4] = {a0.x, a0.y, a1.x, a1.y};
#pragma unroll
            for (int i = 0; i < 8; i++)
#pragma unroll
                for (int j = 0; j < 4; j++) ffma2(acc[i][j], wa[i], av[j]);
        }
        __syncthreads();
    }

    // unpack + bias
    float fl[8][8];
#pragma unroll
    for (int i = 0; i < 8; i++) {
        float bi = bias[ty * 8 + i];
#pragma unroll
        for (int j = 0; j < 4; j++) {
            float2 t = unpack2(acc[i][j]);
            fl[i][2 * j]     = t.x + bi;
            fl[i][2 * j + 1] = t.y + bi;
        }
    }

    // per-column sum of squares via smem tree (no atomics)
#pragma unroll
    for (int j = 0; j < 8; j++) {
        float p = 0.f;
#pragma unroll
        for (int i = 0; i < 8; i++) p += fl[i][j] * fl[i][j];
        psum[ty][tx * 8 + j] = p;
    }
    __syncthreads();
    if (tid < 64) {
        float s2 = 0.f;
#pragma unroll
        for (int t = 0; t < 32; t++) s2 += psum[t][tid];
        invs[tid] = 16.0f / fmaxf(sqrtf(s2), 1e-12f);
    }
    __syncthreads();

    float* ob = out + (size_t)b * CIN * HW + pos0;
#pragma unroll
    for (int i = 0; i < 8; i++) {
        int row = ty * 8 + i;
        float gr = gout[row];
        *(float4*)(ob + (size_t)row * HW + tx * 8) =
            make_float4(fl[i][0] * invs[tx * 8 + 0] * gr,
                        fl[i][1] * invs[tx * 8 + 1] * gr,
                        fl[i][2] * invs[tx * 8 + 2] * gr,
                        fl[i][3] * invs[tx * 8 + 3] * gr);
        *(float4*)(ob + (size_t)row * HW + tx * 8 + 4) =
            make_float4(fl[i][4] * invs[tx * 8 + 4] * gr,
                        fl[i][5] * invs[tx * 8 + 5] * gr,
                        fl[i][6] * invs[tx * 8 + 6] * gr,
                        fl[i][7] * invs[tx * 8 + 7] * gr);
    }
}

// ---------------------------------------------------------------------------
extern "C" void kernel_launch(void* const* d_in, const int* in_sizes, int n_in,
                              void* d_out, int out_size) {
    const float* x      = (const float*)d_in[0];
    const float* g_in   = (const float*)d_in[1];
    const float* w_qkv  = (const float*)d_in[2];
    const float* mem_kv = (const float*)d_in[3];
    const float* w_out  = (const float*)d_in[4];
    const float* b_out  = (const float*)d_in[5];
    const float* g_out  = (const float*)d_in[6];
    float* out = (float*)d_out;

    float *s_ptr, *wg_ptr, *qkv_ptr, *rmax_ptr, *rinv_ptr, *part_ptr, *ctx_ptr, *att_ptr;
    cudaGetSymbolAddress((void**)&s_ptr,    g_s);
    cudaGetSymbolAddress((void**)&wg_ptr,   g_wg);
    cudaGetSymbolAddress((void**)&qkv_ptr,  g_qkv);
    cudaGetSymbolAddress((void**)&rmax_ptr, g_rmax);
    cudaGetSymbolAddress((void**)&rinv_ptr, g_rinv);
    cudaGetSymbolAddress((void**)&part_ptr, g_part);
    cudaGetSymbolAddress((void**)&ctx_ptr,  g_ctx);
    cudaGetSymbolAddress((void**)&att_ptr,  g_att);

    colscale_kernel<<<(BATCH * HW + 255) / 256, 256>>>(x, s_ptr);
    wg_kernel<<<(O3 * CIN + 255) / 256, 256>>>(w_qkv, g_in, wg_ptr);
    qkv_gemm_kernel<<<dim3(HW / BN, O3 / BM, BATCH), 256>>>(wg_ptr, x, s_ptr, qkv_ptr);
    kstats_kernel<<<dim3(HD, NH, BATCH), 256>>>(qkv_ptr, mem_kv, rmax_ptr, rinv_ptr);
    ctxpart_kernel<<<dim3(NC, NH, BATCH), 256>>>(qkv_ptr, rmax_ptr, part_ptr);
    ctxreduce_kernel<<<dim3(NH, BATCH), 256>>>(part_ptr, mem_kv, rmax_ptr, rinv_ptr, ctx_ptr);
    attend_kernel<<<dim3(HW / 64, NH, BATCH), 256>>>(qkv_ptr, ctx_ptr, att_ptr);
    outnorm_kernel<<<dim3(HW / 64, BATCH), 256>>>(w_out, att_ptr, b_out, g_out, out);
}

// round 4
// speedup vs baseline: 1.6847x; 1.4074x over previous
#include <cuda_runtime.h>
#include <cuda_bf16.h>
#include <math.h>
#include <stdint.h>

// Problem constants
#define BATCH 16
#define CIN   256
#define HW    4096
#define O3    1536
#define HID   512
#define NH    8
#define HD    64
#define NMEM  4
#define NC    8
#define CHUNK 512

typedef unsigned long long u64;

// Scratch (device globals — allocation-free rule)
__device__ float g_s[BATCH * HW];
__device__ __nv_bfloat16 g_w1[O3 * CIN];
__device__ __nv_bfloat16 g_w2[O3 * CIN];
__device__ __nv_bfloat16 g_x1[(size_t)BATCH * HW * CIN];   // transposed [b][n][c]
__device__ __nv_bfloat16 g_x2[(size_t)BATCH * HW * CIN];
__device__ float g_qkv[(size_t)BATCH * O3 * HW];           // 402 MB
__device__ float g_rmax[BATCH * NH * HD];
__device__ float g_rinv[BATCH * NH * HD];
__device__ float g_part[(size_t)NC * BATCH * NH * HD * HD];
__device__ float g_ctx[BATCH * NH * HD * HD];
__device__ float g_att[(size_t)BATCH * HID * HW];          // 134 MB

// ---- packed f32x2 helpers ------------------------------------------------
__device__ __forceinline__ u64 pack_dup(float v) {
    u64 r; asm("mov.b64 %0, {%1, %2};" : "=l"(r) : "f"(v), "f"(v)); return r;
}
__device__ __forceinline__ void ffma2(u64& d, u64 a, u64 b) {
    asm("fma.rn.f32x2 %0, %1, %2, %0;" : "+l"(d) : "l"(a), "l"(b));
}
__device__ __forceinline__ float2 unpack2(u64 v) {
    float2 f; asm("mov.b64 {%0, %1}, %2;" : "=f"(f.x), "=f"(f.y) : "l"(v)); return f;
}

// ---- mma.sync helpers ------------------------------------------------------
__device__ __forceinline__ uint32_t smem_u32(const void* p) {
    uint32_t a;
    asm("{ .reg .u64 t; cvta.to.shared.u64 t, %1; cvt.u32.u64 %0, t; }"
        : "=r"(a) : "l"(p));
    return a;
}
__device__ __forceinline__ void ldm4(uint32_t* r, uint32_t addr) {
    asm volatile("ldmatrix.sync.aligned.m8n8.x4.shared.b16 {%0,%1,%2,%3}, [%4];"
                 : "=r"(r[0]), "=r"(r[1]), "=r"(r[2]), "=r"(r[3]) : "r"(addr));
}
__device__ __forceinline__ void mma_bf16(float* c, const uint32_t* a,
                                         uint32_t b0, uint32_t b1) {
    asm volatile(
        "mma.sync.aligned.m16n8k16.row.col.f32.bf16.bf16.f32 "
        "{%0,%1,%2,%3}, {%4,%5,%6,%7}, {%8,%9}, {%0,%1,%2,%3};"
        : "+f"(c[0]), "+f"(c[1]), "+f"(c[2]), "+f"(c[3])
        : "r"(a[0]), "r"(a[1]), "r"(a[2]), "r"(a[3]), "r"(b0), "r"(b1));
}

// ---------------------------------------------------------------------------
// Kernel 1: per-position rmsnorm scale
// ---------------------------------------------------------------------------
__global__ __launch_bounds__(256) void colscale_kernel(const float* __restrict__ x,
                                                       float* __restrict__ s) {
    int idx = blockIdx.x * 256 + threadIdx.x;
    if (idx >= BATCH * HW) return;
    int b = idx >> 12, pos = idx & (HW - 1);
    const float* p = x + (size_t)b * CIN * HW + pos;
    float acc = 0.f;
#pragma unroll 8
    for (int c = 0; c < CIN; c++) {
        float v = p[(size_t)c * HW];
        acc += v * v;
    }
    s[idx] = 16.0f / fmaxf(sqrtf(acc), 1e-12f);
}

// ---------------------------------------------------------------------------
// Kernel 1b: W fold + bf16 2-way split
// ---------------------------------------------------------------------------
__global__ __launch_bounds__(256) void wconv_kernel(const float* __restrict__ w,
                                                    const float* __restrict__ g,
                                                    __nv_bfloat16* __restrict__ w1,
                                                    __nv_bfloat16* __restrict__ w2) {
    int i = blockIdx.x * 256 + threadIdx.x;
    if (i >= O3 * CIN) return;
    float wg = w[i] * g[i & (CIN - 1)];
    __nv_bfloat16 h = __float2bfloat16_rn(wg);
    w1[i] = h;
    w2[i] = __float2bfloat16_rn(wg - __bfloat162float(h));
}

// ---------------------------------------------------------------------------
// Kernel 1c: X transpose to [b][n][c], fold rmsnorm scale, bf16 2-way split
// ---------------------------------------------------------------------------
__global__ __launch_bounds__(256) void xconv_kernel(const float* __restrict__ x,
                                                    const float* __restrict__ s,
                                                    __nv_bfloat16* __restrict__ x1,
                                                    __nv_bfloat16* __restrict__ x2) {
    int b = blockIdx.z;
    int c0 = blockIdx.y * 32, n0 = blockIdx.x * 32;
    __shared__ float t[32][33];
    int tid = threadIdx.x;
    int tx = tid & 31, ty = tid >> 5;
#pragma unroll
    for (int i = 0; i < 4; i++) {
        int c = ty + i * 8;
        t[c][tx] = x[((size_t)b * CIN + c0 + c) * HW + n0 + tx];
    }
    __syncthreads();
#pragma unroll
    for (int i = 0; i < 4; i++) {
        int nr = ty + i * 8;
        float sv = s[b * HW + n0 + nr];
        float v = t[tx][nr] * sv;
        __nv_bfloat16 h = __float2bfloat16_rn(v);
        size_t o = ((size_t)b * HW + n0 + nr) * CIN + c0 + tx;
        x1[o] = h;
        x2[o] = __float2bfloat16_rn(v - __bfloat162float(h));
    }
}

// ---------------------------------------------------------------------------
// Kernel 2: QKV GEMM via mma.sync bf16, exact 2-way split (3 products).
// C[1536,4096] = Wg @ Xs per batch. CTA tile 128x128, K-tile 64.
// 8 warps (4m x 2n), warp tile 32x64, m16n8k16.
// ---------------------------------------------------------------------------
#define LDK   72                      // padded bf16 stride (144B, conflict-free)
#define TILEB (128 * LDK * 2)         // 18432 B per split tile
#define SMA1  0
#define SMA2  (TILEB)
#define SMB1  (2 * TILEB)
#define SMB2  (3 * TILEB)
#define SMTOT (4 * TILEB)             // 73728 B

__device__ __forceinline__ void copy_tile64(char* dst, const char* src, int tid) {
    // 128 rows x 64 bf16 (128B = 8x16B per row); 256 threads x 4 uint4
#pragma unroll
    for (int j = 0; j < 4; j++) {
        int f = tid + j * 256;
        int row = f >> 3, seg = f & 7;
        *(uint4*)(dst + row * (LDK * 2) + seg * 16) =
            *(const uint4*)(src + (size_t)row * (CIN * 2) + seg * 16);
    }
}

__global__ void __launch_bounds__(256, 1)
qkv_mma_kernel(const __nv_bfloat16* __restrict__ w1,
               const __nv_bfloat16* __restrict__ w2,
               const __nv_bfloat16* __restrict__ x1,
               const __nv_bfloat16* __restrict__ x2,
               float* __restrict__ out) {
    extern __shared__ char smem[];
    uint32_t sb = smem_u32(smem);
    int tid = threadIdx.x;
    int warp = tid >> 5, lane = tid & 31;
    int b = blockIdx.z;
    int rowBase = blockIdx.y * 128;
    int colBase = blockIdx.x * 128;

    const char* As1 = (const char*)(w1 + (size_t)rowBase * CIN);
    const char* As2 = (const char*)(w2 + (size_t)rowBase * CIN);
    const char* Bs1 = (const char*)(x1 + ((size_t)b * HW + colBase) * CIN);
    const char* Bs2 = (const char*)(x2 + ((size_t)b * HW + colBase) * CIN);

    int mwarp = (warp >> 1) * 32;
    int nwarp = (warp & 1) * 64;

    float acc[2][8][4];
#pragma unroll
    for (int mi = 0; mi < 2; mi++)
#pragma unroll
        for (int nf = 0; nf < 8; nf++)
#pragma unroll
            for (int q = 0; q < 4; q++) acc[mi][nf][q] = 0.f;

    // ldmatrix lane offsets
    int lrow = lane & 7, mat = lane >> 3;
    int frow = (mat & 1) * 8 + lrow;      // row within 16-row fragment
    int fk   = (mat >> 1) * 8;            // k offset (0 or 8)

    for (int k0 = 0; k0 < CIN; k0 += 64) {
        copy_tile64(smem + SMA1, As1 + k0 * 2, tid);
        copy_tile64(smem + SMA2, As2 + k0 * 2, tid);
        copy_tile64(smem + SMB1, Bs1 + k0 * 2, tid);
        copy_tile64(smem + SMB2, Bs2 + k0 * 2, tid);
        __syncthreads();

#pragma unroll
        for (int ks = 0; ks < 4; ks++) {
            int kk = ks * 16 + fk;
            uint32_t a1[2][4], a2[2][4];
#pragma unroll
            for (int mi = 0; mi < 2; mi++) {
                uint32_t off = (uint32_t)((mwarp + mi * 16 + frow) * (LDK * 2) + kk * 2);
                ldm4(a1[mi], sb + SMA1 + off);
                ldm4(a2[mi], sb + SMA2 + off);
            }
            uint32_t b1[4][4], b2[4][4];
#pragma unroll
            for (int nb = 0; nb < 4; nb++) {
                uint32_t off = (uint32_t)((nwarp + nb * 16 + frow) * (LDK * 2) + kk * 2);
                ldm4(b1[nb], sb + SMB1 + off);
                ldm4(b2[nb], sb + SMB2 + off);
            }
#pragma unroll
            for (int mi = 0; mi < 2; mi++)
#pragma unroll
                for (int nf = 0; nf < 8; nf++) {
                    int nb = nf >> 1, hi = nf & 1;
                    mma_bf16(acc[mi][nf], a1[mi], b1[nb][hi], b1[nb][hi + 2]);
                    mma_bf16(acc[mi][nf], a1[mi], b2[nb][hi], b2[nb][hi + 2]);
                    mma_bf16(acc[mi][nf], a2[mi], b1[nb][hi], b1[nb][hi + 2]);
                }
        }
        __syncthreads();
    }

    // Epilogue: accum lane mapping m16n8: c0,c1=(m,n),(m,n+1); c2,c3=(m+8,*)
    float* obase = out + (size_t)b * O3 * HW;
#pragma unroll
    for (int mi = 0; mi < 2; mi++) {
        int row = rowBase + mwarp + mi * 16 + (lane >> 2);
#pragma unroll
        for (int nf = 0; nf < 8; nf++) {
            int col = colBase + nwarp + nf * 8 + (lane & 3) * 2;
            *(float2*)(obase + (size_t)row * HW + col) =
                make_float2(acc[mi][nf][0], acc[mi][nf][1]);
            *(float2*)(obase + (size_t)(row + 8) * HW + col) =
                make_float2(acc[mi][nf][2], acc[mi][nf][3]);
        }
    }
}

// ---------------------------------------------------------------------------
// Kernel 3a: k-softmax stats per (b,h,d) row
// ---------------------------------------------------------------------------
__global__ __launch_bounds__(256) void kstats_kernel(const float* __restrict__ qkv,
                                                     const float* __restrict__ memkv,
                                                     float* __restrict__ rmax,
                                                     float* __restrict__ rinv) {
    int d = blockIdx.x, h = blockIdx.y, b = blockIdx.z;
    int tid = threadIdx.x;
    const float* kr = qkv + ((size_t)b * O3 + HID + h * HD + d) * HW;
    const float* MK = memkv + ((size_t)h * HD + d) * NMEM;

    float v[16];
#pragma unroll
    for (int i = 0; i < 16; i++) v[i] = kr[i * 256 + tid];
    float m = v[0];
#pragma unroll
    for (int i = 1; i < 16; i++) m = fmaxf(m, v[i]);
    if (tid < NMEM) m = fmaxf(m, MK[tid]);

    __shared__ float red[8];
#pragma unroll
    for (int o = 16; o; o >>= 1) m = fmaxf(m, __shfl_xor_sync(0xFFFFFFFFu, m, o));
    if ((tid & 31) == 0) red[tid >> 5] = m;
    __syncthreads();
    if (tid == 0) {
        float t = red[0];
#pragma unroll
        for (int i = 1; i < 8; i++) t = fmaxf(t, red[i]);
        red[0] = t;
    }
    __syncthreads();
    m = red[0];
    __syncthreads();

    float ss = 0.f;
#pragma unroll
    for (int i = 0; i < 16; i++) ss += __expf(v[i] - m);
    if (tid < NMEM) ss += __expf(MK[tid] - m);
#pragma unroll
    for (int o = 16; o; o >>= 1) ss += __shfl_xor_sync(0xFFFFFFFFu, ss, o);
    if ((tid & 31) == 0) red[tid >> 5] = ss;
    __syncthreads();
    if (tid == 0) {
        float t = 0.f;
#pragma unroll
        for (int i = 0; i < 8; i++) t += red[i];
        int idx = (b * NH + h) * HD + d;
        rmax[idx] = m;
        rinv[idx] = 1.0f / t;
    }
}

// ---------------------------------------------------------------------------
// Kernel 3b: partial context over n chunks
// ---------------------------------------------------------------------------
__global__ __launch_bounds__(256) void ctxpart_kernel(const float* __restrict__ qkv,
                                                      const float* __restrict__ rmax,
                                                      float* __restrict__ part) {
    int c = blockIdx.x, h = blockIdx.y, b = blockIdx.z;
    const float* K = qkv + ((size_t)b * O3 + HID + h * HD) * HW;
    const float* V = qkv + ((size_t)b * O3 + 2 * HID + h * HD) * HW;

    __shared__ __align__(16) float Kt[64][68];
    __shared__ __align__(16) float Vt[64][68];
    __shared__ float rm[64];

    int tid = threadIdx.x;
    if (tid < 64) rm[tid] = rmax[(b * NH + h) * HD + tid];
    __syncthreads();

    int tx = tid & 15, ty = tid >> 4;
    u64 acc[4][2];
#pragma unroll
    for (int i = 0; i < 4; i++) { acc[i][0] = 0ULL; acc[i][1] = 0ULL; }

    for (int nt = 0; nt < CHUNK / 64; nt++) {
        int n0 = c * CHUNK + nt * 64;
#pragma unroll
        for (int l = 0; l < 16; l++) {
            int lin = l * 256 + tid;
            int d = lin >> 6, j = lin & 63;
            Kt[j][d] = __expf(K[(size_t)d * HW + n0 + j] - rm[d]);
            Vt[j][d] = V[(size_t)d * HW + n0 + j];
        }
        __syncthreads();
#pragma unroll 4
        for (int j = 0; j < 64; j++) {
            float4 kf = *(const float4*)(&Kt[j][ty * 4]);
            u64 k0 = pack_dup(kf.x), k1 = pack_dup(kf.y);
            u64 k2 = pack_dup(kf.z), k3 = pack_dup(kf.w);
            ulonglong2 vv = *(const ulonglong2*)(&Vt[j][tx * 4]);
            ffma2(acc[0][0], k0, vv.x); ffma2(acc[0][1], k0, vv.y);
            ffma2(acc[1][0], k1, vv.x); ffma2(acc[1][1], k1, vv.y);
            ffma2(acc[2][0], k2, vv.x); ffma2(acc[2][1], k2, vv.y);
            ffma2(acc[3][0], k3, vv.x); ffma2(acc[3][1], k3, vv.y);
        }
        __syncthreads();
    }

    float* pb = part + ((size_t)c * BATCH * NH + b * NH + h) * (HD * HD);
#pragma unroll
    for (int i = 0; i < 4; i++) {
        float2 a = unpack2(acc[i][0]);
        float2 bb = unpack2(acc[i][1]);
        *(float4*)(&pb[(ty * 4 + i) * HD + tx * 4]) = make_float4(a.x, a.y, bb.x, bb.y);
    }
}

// ---------------------------------------------------------------------------
// Kernel 3c: reduce partials + mem-kv tail + rinv scaling -> ctx
// ---------------------------------------------------------------------------
__global__ __launch_bounds__(256) void ctxreduce_kernel(const float* __restrict__ part,
                                                        const float* __restrict__ memkv,
                                                        const float* __restrict__ rmax,
                                                        const float* __restrict__ rinv,
                                                        float* __restrict__ ctx) {
    int h = blockIdx.x, b = blockIdx.y;
    __shared__ float mkx[64][4];
    __shared__ float mvs[64][4];
    __shared__ float riv[64];
    int tid = threadIdx.x;
    if (tid < 64) riv[tid] = rinv[(b * NH + h) * HD + tid];
    {
        int d = tid >> 2, j = tid & 3;
        mkx[d][j] = __expf(memkv[((size_t)h * HD + d) * NMEM + j] -
                           rmax[(b * NH + h) * HD + d]);
        mvs[d][j] = memkv[(size_t)NH * HD * NMEM + ((size_t)h * HD + d) * NMEM + j];
    }
    __syncthreads();
    size_t base = (size_t)(b * NH + h) * (HD * HD);
    for (int l = tid; l < HD * HD; l += 256) {
        int d = l >> 6, e = l & 63;
        float s2 = 0.f;
#pragma unroll
        for (int cc = 0; cc < NC; cc++)
            s2 += part[(size_t)cc * BATCH * NH * HD * HD + base + l];
#pragma unroll
        for (int j = 0; j < 4; j++) s2 += mkx[d][j] * mvs[e][j];
        ctx[base + l] = s2 * riv[d];
    }
}

// ---------------------------------------------------------------------------
// Kernel 4: q-softmax over d + out[e][p] = sum_d ctx[d][e]*qs[d][p]
// ---------------------------------------------------------------------------
__global__ __launch_bounds__(256) void attend_kernel(const float* __restrict__ qkv,
                                                     const float* __restrict__ ctx,
                                                     float* __restrict__ att) {
    int pos0 = blockIdx.x * 64;
    int h = blockIdx.y, b = blockIdx.z;
    const float* Q = qkv + ((size_t)b * O3 + h * HD) * HW;
    const float* cb = ctx + (size_t)(b * NH + h) * HD * HD;

    __shared__ __align__(16) float cs[64][68];
    __shared__ __align__(16) float qs[64][68];

    int tid = threadIdx.x;
    for (int l = tid; l < HD * HD; l += 256) {
        int d = l >> 6, e = l & 63;
        cs[d][e] = cb[l];
        qs[d][e] = Q[(size_t)d * HW + pos0 + e];
    }
    __syncthreads();

    if (tid < 64) {
        float m = -1e30f;
#pragma unroll
        for (int d = 0; d < HD; d++) m = fmaxf(m, qs[d][tid]);
        float ss = 0.f;
#pragma unroll
        for (int d = 0; d < HD; d++) ss += __expf(qs[d][tid] - m);
        float inv = 0.125f / ss;
#pragma unroll
        for (int d = 0; d < HD; d++)
            qs[d][tid] = __expf(qs[d][tid] - m) * inv;
    }
    __syncthreads();

    int tx = tid & 15, ty = tid >> 4;
    u64 acc[4][2];
#pragma unroll
    for (int i = 0; i < 4; i++) { acc[i][0] = 0ULL; acc[i][1] = 0ULL; }

#pragma unroll 4
    for (int d = 0; d < HD; d++) {
        float4 cf = *(const float4*)(&cs[d][ty * 4]);
        u64 c0 = pack_dup(cf.x), c1 = pack_dup(cf.y);
        u64 c2 = pack_dup(cf.z), c3 = pack_dup(cf.w);
        ulonglong2 qq = *(const ulonglong2*)(&qs[d][tx * 4]);
        ffma2(acc[0][0], c0, qq.x); ffma2(acc[0][1], c0, qq.y);
        ffma2(acc[1][0], c1, qq.x); ffma2(acc[1][1], c1, qq.y);
        ffma2(acc[2][0], c2, qq.x); ffma2(acc[2][1], c2, qq.y);
        ffma2(acc[3][0], c3, qq.x); ffma2(acc[3][1], c3, qq.y);
    }

    float* ob = att + ((size_t)b * HID + h * HD) * HW + pos0;
#pragma unroll
    for (int i = 0; i < 4; i++) {
        float2 a = unpack2(acc[i][0]);
        float2 bb = unpack2(acc[i][1]);
        *(float4*)(ob + (size_t)(ty * 4 + i) * HW + tx * 4) =
            make_float4(a.x, a.y, bb.x, bb.y);
    }
}

// ---------------------------------------------------------------------------
// Kernel 5: out GEMM + bias + fused rmsnorm
// ---------------------------------------------------------------------------
__global__ __launch_bounds__(256) void outnorm_kernel(const float* __restrict__ Wo,
                                                      const float* __restrict__ att,
                                                      const float* __restrict__ bias,
                                                      const float* __restrict__ gout,
                                                      float* __restrict__ out) {
    int b = blockIdx.y;
    int pos0 = blockIdx.x * 64;
    const float* Ab = att + (size_t)b * HID * HW;

    __shared__ __align__(16) float Ws[16][256];
    __shared__ __align__(16) float As[16][64];
    __shared__ float psum[32][65];
    __shared__ float invs[64];

    int tid = threadIdx.x;
    int tx = tid & 7, ty = tid >> 3;

    u64 acc[8][4];
#pragma unroll
    for (int i = 0; i < 8; i++)
#pragma unroll
        for (int j = 0; j < 4; j++) acc[i][j] = 0ULL;

    for (int k0 = 0; k0 < HID; k0 += 16) {
#pragma unroll
        for (int l = 0; l < 4; l++) {
            int lin = tid + l * 256;
            int r = lin >> 2, kq = lin & 3;
            float4 w = *(const float4*)(Wo + (size_t)r * HID + k0 + kq * 4);
            Ws[kq * 4 + 0][r] = w.x;
            Ws[kq * 4 + 1][r] = w.y;
            Ws[kq * 4 + 2][r] = w.z;
            Ws[kq * 4 + 3][r] = w.w;
        }
        {
            int kr = tid >> 4, cc = (tid & 15) * 4;
            *(float4*)(&As[kr][cc]) =
                *(const float4*)(Ab + (size_t)(k0 + kr) * HW + pos0 + cc);
        }
        __syncthreads();
#pragma unroll
        for (int kk = 0; kk < 16; kk++) {
            float wf[8];
            *(float4*)(wf)     = *(const float4*)(&Ws[kk][ty * 8]);
            *(float4*)(wf + 4) = *(const float4*)(&Ws[kk][ty * 8 + 4]);
            u64 wa[8];
#pragma unroll
            for (int i = 0; i < 8; i++) wa[i] = pack_dup(wf[i]);
            ulonglong2 a0 = *(const ulonglong2*)(&As[kk][tx * 8]);
            ulonglong2 a1 = *(const ulonglong2*)(&As[kk][tx * 8 + 4]);
            u64 av[4] = {a0.x, a0.y, a1.x, a1.y};
#pragma unroll
            for (int i = 0; i < 8; i++)
#pragma unroll
                for (int j = 0; j < 4; j++) ffma2(acc[i][j], wa[i], av[j]);
        }
        __syncthreads();
    }

    float fl[8][8];
#pragma unroll
    for (int i = 0; i < 8; i++) {
        float bi = bias[ty * 8 + i];
#pragma unroll
        for (int j = 0; j < 4; j++) {
            float2 t = unpack2(acc[i][j]);
            fl[i][2 * j]     = t.x + bi;
            fl[i][2 * j + 1] = t.y + bi;
        }
    }

#pragma unroll
    for (int j = 0; j < 8; j++) {
        float p = 0.f;
#pragma unroll
        for (int i = 0; i < 8; i++) p += fl[i][j] * fl[i][j];
        psum[ty][tx * 8 + j] = p;
    }
    __syncthreads();
    if (tid < 64) {
        float s2 = 0.f;
#pragma unroll
        for (int t = 0; t < 32; t++) s2 += psum[t][tid];
        invs[tid] = 16.0f / fmaxf(sqrtf(s2), 1e-12f);
    }
    __syncthreads();

    float* ob = out + (size_t)b * CIN * HW + pos0;
#pragma unroll
    for (int i = 0; i < 8; i++) {
        int row = ty * 8 + i;
        float gr = gout[row];
        *(float4*)(ob + (size_t)row * HW + tx * 8) =
            make_float4(fl[i][0] * invs[tx * 8 + 0] * gr,
                        fl[i][1] * invs[tx * 8 + 1] * gr,
                        fl[i][2] * invs[tx * 8 + 2] * gr,
                        fl[i][3] * invs[tx * 8 + 3] * gr);
        *(float4*)(ob + (size_t)row * HW + tx * 8 + 4) =
            make_float4(fl[i][4] * invs[tx * 8 + 4] * gr,
                        fl[i][5] * invs[tx * 8 + 5] * gr,
                        fl[i][6] * invs[tx * 8 + 6] * gr,
                        fl[i][7] * invs[tx * 8 + 7] * gr);
    }
}

// ---------------------------------------------------------------------------
extern "C" void kernel_launch(void* const* d_in, const int* in_sizes, int n_in,
                              void* d_out, int out_size) {
    const float* x      = (const float*)d_in[0];
    const float* g_in   = (const float*)d_in[1];
    const float* w_qkv  = (const float*)d_in[2];
    const float* mem_kv = (const float*)d_in[3];
    const float* w_out  = (const float*)d_in[4];
    const float* b_out  = (const float*)d_in[5];
    const float* g_out  = (const float*)d_in[6];
    float* out = (float*)d_out;

    float *s_ptr, *qkv_ptr, *rmax_ptr, *rinv_ptr, *part_ptr, *ctx_ptr, *att_ptr;
    __nv_bfloat16 *w1_ptr, *w2_ptr, *x1_ptr, *x2_ptr;
    cudaGetSymbolAddress((void**)&s_ptr,    g_s);
    cudaGetSymbolAddress((void**)&w1_ptr,   g_w1);
    cudaGetSymbolAddress((void**)&w2_ptr,   g_w2);
    cudaGetSymbolAddress((void**)&x1_ptr,   g_x1);
    cudaGetSymbolAddress((void**)&x2_ptr,   g_x2);
    cudaGetSymbolAddress((void**)&qkv_ptr,  g_qkv);
    cudaGetSymbolAddress((void**)&rmax_ptr, g_rmax);
    cudaGetSymbolAddress((void**)&rinv_ptr, g_rinv);
    cudaGetSymbolAddress((void**)&part_ptr, g_part);
    cudaGetSymbolAddress((void**)&ctx_ptr,  g_ctx);
    cudaGetSymbolAddress((void**)&att_ptr,  g_att);

    cudaFuncSetAttribute(qkv_mma_kernel,
                         cudaFuncAttributeMaxDynamicSharedMemorySize, SMTOT);

    colscale_kernel<<<(BATCH * HW + 255) / 256, 256>>>(x, s_ptr);
    wconv_kernel<<<(O3 * CIN + 255) / 256, 256>>>(w_qkv, g_in, w1_ptr, w2_ptr);
    xconv_kernel<<<dim3(HW / 32, CIN / 32, BATCH), 256>>>(x, s_ptr, x1_ptr, x2_ptr);
    qkv_mma_kernel<<<dim3(HW / 128, O3 / 128, BATCH), 256, SMTOT>>>(
        w1_ptr, w2_ptr, x1_ptr, x2_ptr, qkv_ptr);
    kstats_kernel<<<dim3(HD, NH, BATCH), 256>>>(qkv_ptr, mem_kv, rmax_ptr, rinv_ptr);
    ctxpart_kernel<<<dim3(NC, NH, BATCH), 256>>>(qkv_ptr, rmax_ptr, part_ptr);
    ctxreduce_kernel<<<dim3(NH, BATCH), 256>>>(part_ptr, mem_kv, rmax_ptr, rinv_ptr, ctx_ptr);
    attend_kernel<<<dim3(HW / 64, NH, BATCH), 256>>>(qkv_ptr, ctx_ptr, att_ptr);
    outnorm_kernel<<<dim3(HW / 64, BATCH), 256>>>(w_out, att_ptr, b_out, g_out, out);
}

// round 5
// speedup vs baseline: 1.9698x; 1.1692x over previous
#include <cuda_runtime.h>
#include <cuda_bf16.h>
#include <math.h>
#include <stdint.h>
#include <string.h>

// Problem constants
#define BATCH 16
#define CIN   256
#define HW    4096
#define O3    1536
#define HID   512
#define NH    8
#define HD    64
#define NMEM  4
#define NC    8
#define CHUNK 512

typedef unsigned long long u64;

// Scratch (device globals — allocation-free rule)
__device__ float g_s[BATCH * HW];
__device__ __nv_bfloat16 g_w1[O3 * CIN];
__device__ __nv_bfloat16 g_w2[O3 * CIN];
__device__ __nv_bfloat16 g_wo1[CIN * HID];
__device__ __nv_bfloat16 g_wo2[CIN * HID];
__device__ __nv_bfloat16 g_x1[(size_t)BATCH * HW * CIN];   // transposed [b][n][c]
__device__ __nv_bfloat16 g_x2[(size_t)BATCH * HW * CIN];
__device__ float g_qkv[(size_t)BATCH * O3 * HW];           // 402 MB
__device__ float g_rmax[BATCH * NH * HD];
__device__ float g_rinv[BATCH * NH * HD];
__device__ float g_part[(size_t)NC * BATCH * NH * HD * HD];
__device__ float g_ctx[BATCH * NH * HD * HD];
__device__ __nv_bfloat16 g_a1[(size_t)BATCH * HW * HID];   // att^T split [b][pos][hid]
__device__ __nv_bfloat16 g_a2[(size_t)BATCH * HW * HID];

// ---- packed f32x2 helpers ------------------------------------------------
__device__ __forceinline__ u64 pack_dup(float v) {
    u64 r; asm("mov.b64 %0, {%1, %2};" : "=l"(r) : "f"(v), "f"(v)); return r;
}
__device__ __forceinline__ void ffma2(u64& d, u64 a, u64 b) {
    asm("fma.rn.f32x2 %0, %1, %2, %0;" : "+l"(d) : "l"(a), "l"(b));
}
__device__ __forceinline__ float2 unpack2(u64 v) {
    float2 f; asm("mov.b64 {%0, %1}, %2;" : "=f"(f.x), "=f"(f.y) : "l"(v)); return f;
}

// ---- mma.sync helpers ------------------------------------------------------
__device__ __forceinline__ uint32_t smem_u32(const void* p) {
    uint32_t a;
    asm("{ .reg .u64 t; cvta.to.shared.u64 t, %1; cvt.u32.u64 %0, t; }"
        : "=r"(a) : "l"(p));
    return a;
}
__device__ __forceinline__ void ldm4(uint32_t* r, uint32_t addr) {
    asm volatile("ldmatrix.sync.aligned.m8n8.x4.shared.b16 {%0,%1,%2,%3}, [%4];"
                 : "=r"(r[0]), "=r"(r[1]), "=r"(r[2]), "=r"(r[3]) : "r"(addr));
}
__device__ __forceinline__ void mma_bf16(float* c, const uint32_t* a,
                                         uint32_t b0, uint32_t b1) {
    asm volatile(
        "mma.sync.aligned.m16n8k16.row.col.f32.bf16.bf16.f32 "
        "{%0,%1,%2,%3}, {%4,%5,%6,%7}, {%8,%9}, {%0,%1,%2,%3};"
        : "+f"(c[0]), "+f"(c[1]), "+f"(c[2]), "+f"(c[3])
        : "r"(a[0]), "r"(a[1]), "r"(a[2]), "r"(a[3]), "r"(b0), "r"(b1));
}
__device__ __forceinline__ void cp16(uint32_t dst, const void* src) {
    asm volatile("cp.async.cg.shared.global [%0], [%1], 16;"
                 :: "r"(dst), "l"(src));
}
#define CP_COMMIT() asm volatile("cp.async.commit_group;" ::: "memory")
#define CP_WAIT1()  asm volatile("cp.async.wait_group 1;" ::: "memory")
#define CP_WAIT0()  asm volatile("cp.async.wait_group 0;" ::: "memory")

__device__ __forceinline__ uint32_t pkbf(float lo, float hi) {
    __nv_bfloat162 t = __floats2bfloat162_rn(lo, hi);
    uint32_t r; memcpy(&r, &t, 4); return r;
}

// ---------------------------------------------------------------------------
// Kernel 1: per-position rmsnorm scale
// ---------------------------------------------------------------------------
__global__ __launch_bounds__(256) void colscale_kernel(const float* __restrict__ x,
                                                       float* __restrict__ s) {
    int idx = blockIdx.x * 256 + threadIdx.x;
    if (idx >= BATCH * HW) return;
    int b = idx >> 12, pos = idx & (HW - 1);
    const float* p = x + (size_t)b * CIN * HW + pos;
    float acc = 0.f;
#pragma unroll 8
    for (int c = 0; c < CIN; c++) {
        float v = p[(size_t)c * HW];
        acc += v * v;
    }
    s[idx] = 16.0f / fmaxf(sqrtf(acc), 1e-12f);
}

// ---------------------------------------------------------------------------
// Kernel 1b: W fold + bf16 2-way split
// ---------------------------------------------------------------------------
__global__ __launch_bounds__(256) void wconv_kernel(const float* __restrict__ w,
                                                    const float* __restrict__ g,
                                                    __nv_bfloat16* __restrict__ w1,
                                                    __nv_bfloat16* __restrict__ w2) {
    int i = blockIdx.x * 256 + threadIdx.x;
    if (i >= O3 * CIN) return;
    float wg = w[i] * g[i & (CIN - 1)];
    __nv_bfloat16 h = __float2bfloat16_rn(wg);
    w1[i] = h;
    w2[i] = __float2bfloat16_rn(wg - __bfloat162float(h));
}

// Kernel 1b2: w_out bf16 2-way split
__global__ __launch_bounds__(256) void woconv_kernel(const float* __restrict__ w,
                                                     __nv_bfloat16* __restrict__ w1,
                                                     __nv_bfloat16* __restrict__ w2) {
    int i = blockIdx.x * 256 + threadIdx.x;
    if (i >= CIN * HID) return;
    float v = w[i];
    __nv_bfloat16 h = __float2bfloat16_rn(v);
    w1[i] = h;
    w2[i] = __float2bfloat16_rn(v - __bfloat162float(h));
}

// ---------------------------------------------------------------------------
// Kernel 1c: X transpose to [b][n][c], fold rmsnorm scale, bf16 2-way split
// ---------------------------------------------------------------------------
__global__ __launch_bounds__(256) void xconv_kernel(const float* __restrict__ x,
                                                    const float* __restrict__ s,
                                                    __nv_bfloat16* __restrict__ x1,
                                                    __nv_bfloat16* __restrict__ x2) {
    int b = blockIdx.z;
    int c0 = blockIdx.y * 32, n0 = blockIdx.x * 32;
    __shared__ float t[32][33];
    int tid = threadIdx.x;
    int tx = tid & 31, ty = tid >> 5;
#pragma unroll
    for (int i = 0; i < 4; i++) {
        int c = ty + i * 8;
        t[c][tx] = x[((size_t)b * CIN + c0 + c) * HW + n0 + tx];
    }
    __syncthreads();
#pragma unroll
    for (int i = 0; i < 4; i++) {
        int nr = ty + i * 8;
        float sv = s[b * HW + n0 + nr];
        float v = t[tx][nr] * sv;
        __nv_bfloat16 h = __float2bfloat16_rn(v);
        size_t o = ((size_t)b * HW + n0 + nr) * CIN + c0 + tx;
        x1[o] = h;
        x2[o] = __float2bfloat16_rn(v - __bfloat162float(h));
    }
}

// ---------------------------------------------------------------------------
// Kernel 2: QKV GEMM via mma.sync bf16 split, cp.async double-buffered.
// CTA tile 128x128, K-tile 64, 2 stages.
// ---------------------------------------------------------------------------
#define LDK    72
#define TILEB  (128 * LDK * 2)        // 18432
#define STAGEB (4 * TILEB)            // 73728
#define QSMTOT (2 * STAGEB)           // 147456
#define OFF_A1 0
#define OFF_A2 TILEB
#define OFF_B1 (2 * TILEB)
#define OFF_B2 (3 * TILEB)

__global__ void __launch_bounds__(256)
qkv_mma_kernel(const __nv_bfloat16* __restrict__ w1,
               const __nv_bfloat16* __restrict__ w2,
               const __nv_bfloat16* __restrict__ x1,
               const __nv_bfloat16* __restrict__ x2,
               float* __restrict__ out) {
    extern __shared__ char smem[];
    uint32_t sb = smem_u32(smem);
    int tid = threadIdx.x;
    int warp = tid >> 5, lane = tid & 31;
    int b = blockIdx.z;
    int rowBase = blockIdx.y * 128;
    int colBase = blockIdx.x * 128;

    const char* src[4] = {
        (const char*)(w1 + (size_t)rowBase * CIN),
        (const char*)(w2 + (size_t)rowBase * CIN),
        (const char*)(x1 + ((size_t)b * HW + colBase) * CIN),
        (const char*)(x2 + ((size_t)b * HW + colBase) * CIN)};

    int lrow = tid >> 3, lseg = tid & 7;  // 32 rows x 8 segs covered per 256-thr pass

    auto load_stage = [&](int st, int k0) {
        uint32_t dbase = sb + st * STAGEB;
#pragma unroll
        for (int t4 = 0; t4 < 4; t4++) {
            const char* sp = src[t4] + k0 * 2 + lseg * 16;
            uint32_t dp = dbase + t4 * TILEB + lrow * (LDK * 2) + lseg * 16;
#pragma unroll
            for (int j = 0; j < 4; j++)
                cp16(dp + j * 32 * (LDK * 2), sp + (size_t)(lrow + j * 32) * (CIN * 2));
        }
    };

    int mwarp = (warp >> 1) * 32;
    int nwarp = (warp & 1) * 64;

    float acc[2][8][4];
#pragma unroll
    for (int mi = 0; mi < 2; mi++)
#pragma unroll
        for (int nf = 0; nf < 8; nf++)
#pragma unroll
            for (int q = 0; q < 4; q++) acc[mi][nf][q] = 0.f;

    int flrow = lane & 7, mat = lane >> 3;
    int frow = (mat & 1) * 8 + flrow;
    int fk   = (mat >> 1) * 8;

    load_stage(0, 0);
    CP_COMMIT();

    for (int kt = 0; kt < 4; kt++) {
        if (kt < 3) {
            load_stage((kt + 1) & 1, (kt + 1) * 64);
            CP_COMMIT();
            CP_WAIT1();
        } else {
            CP_WAIT0();
        }
        __syncthreads();
        uint32_t stb = sb + (kt & 1) * STAGEB;

#pragma unroll
        for (int ks = 0; ks < 4; ks++) {
            int kk = ks * 16 + fk;
            uint32_t a1[2][4], a2[2][4];
#pragma unroll
            for (int mi = 0; mi < 2; mi++) {
                uint32_t off = (uint32_t)((mwarp + mi * 16 + frow) * (LDK * 2) + kk * 2);
                ldm4(a1[mi], stb + OFF_A1 + off);
                ldm4(a2[mi], stb + OFF_A2 + off);
            }
            uint32_t b1[4][4], b2[4][4];
#pragma unroll
            for (int nb = 0; nb < 4; nb++) {
                uint32_t off = (uint32_t)((nwarp + nb * 16 + frow) * (LDK * 2) + kk * 2);
                ldm4(b1[nb], stb + OFF_B1 + off);
                ldm4(b2[nb], stb + OFF_B2 + off);
            }
#pragma unroll
            for (int mi = 0; mi < 2; mi++)
#pragma unroll
                for (int nf = 0; nf < 8; nf++) {
                    int nb = nf >> 1, hi = nf & 1;
                    mma_bf16(acc[mi][nf], a1[mi], b1[nb][hi], b1[nb][hi + 2]);
                    mma_bf16(acc[mi][nf], a1[mi], b2[nb][hi], b2[nb][hi + 2]);
                    mma_bf16(acc[mi][nf], a2[mi], b1[nb][hi], b1[nb][hi + 2]);
                }
        }
        __syncthreads();
    }

    float* obase = out + (size_t)b * O3 * HW;
#pragma unroll
    for (int mi = 0; mi < 2; mi++) {
        int row = rowBase + mwarp + mi * 16 + (lane >> 2);
#pragma unroll
        for (int nf = 0; nf < 8; nf++) {
            int col = colBase + nwarp + nf * 8 + (lane & 3) * 2;
            *(float2*)(obase + (size_t)row * HW + col) =
                make_float2(acc[mi][nf][0], acc[mi][nf][1]);
            *(float2*)(obase + (size_t)(row + 8) * HW + col) =
                make_float2(acc[mi][nf][2], acc[mi][nf][3]);
        }
    }
}

// ---------------------------------------------------------------------------
// Kernel 3a: k-softmax stats per (b,h,d) row
// ---------------------------------------------------------------------------
__global__ __launch_bounds__(256) void kstats_kernel(const float* __restrict__ qkv,
                                                     const float* __restrict__ memkv,
                                                     float* __restrict__ rmax,
                                                     float* __restrict__ rinv) {
    int d = blockIdx.x, h = blockIdx.y, b = blockIdx.z;
    int tid = threadIdx.x;
    const float* kr = qkv + ((size_t)b * O3 + HID + h * HD + d) * HW;
    const float* MK = memkv + ((size_t)h * HD + d) * NMEM;

    float v[16];
#pragma unroll
    for (int i = 0; i < 16; i++) v[i] = kr[i * 256 + tid];
    float m = v[0];
#pragma unroll
    for (int i = 1; i < 16; i++) m = fmaxf(m, v[i]);
    if (tid < NMEM) m = fmaxf(m, MK[tid]);

    __shared__ float red[8];
#pragma unroll
    for (int o = 16; o; o >>= 1) m = fmaxf(m, __shfl_xor_sync(0xFFFFFFFFu, m, o));
    if ((tid & 31) == 0) red[tid >> 5] = m;
    __syncthreads();
    if (tid == 0) {
        float t = red[0];
#pragma unroll
        for (int i = 1; i < 8; i++) t = fmaxf(t, red[i]);
        red[0] = t;
    }
    __syncthreads();
    m = red[0];
    __syncthreads();

    float ss = 0.f;
#pragma unroll
    for (int i = 0; i < 16; i++) ss += __expf(v[i] - m);
    if (tid < NMEM) ss += __expf(MK[tid] - m);
#pragma unroll
    for (int o = 16; o; o >>= 1) ss += __shfl_xor_sync(0xFFFFFFFFu, ss, o);
    if ((tid & 31) == 0) red[tid >> 5] = ss;
    __syncthreads();
    if (tid == 0) {
        float t = 0.f;
#pragma unroll
        for (int i = 0; i < 8; i++) t += red[i];
        int idx = (b * NH + h) * HD + d;
        rmax[idx] = m;
        rinv[idx] = 1.0f / t;
    }
}

// ---------------------------------------------------------------------------
// Kernel 3b: partial context over n chunks
// ---------------------------------------------------------------------------
__global__ __launch_bounds__(256) void ctxpart_kernel(const float* __restrict__ qkv,
                                                      const float* __restrict__ rmax,
                                                      float* __restrict__ part) {
    int c = blockIdx.x, h = blockIdx.y, b = blockIdx.z;
    const float* K = qkv + ((size_t)b * O3 + HID + h * HD) * HW;
    const float* V = qkv + ((size_t)b * O3 + 2 * HID + h * HD) * HW;

    __shared__ __align__(16) float Kt[64][68];
    __shared__ __align__(16) float Vt[64][68];
    __shared__ float rm[64];

    int tid = threadIdx.x;
    if (tid < 64) rm[tid] = rmax[(b * NH + h) * HD + tid];
    __syncthreads();

    int tx = tid & 15, ty = tid >> 4;
    u64 acc[4][2];
#pragma unroll
    for (int i = 0; i < 4; i++) { acc[i][0] = 0ULL; acc[i][1] = 0ULL; }

    for (int nt = 0; nt < CHUNK / 64; nt++) {
        int n0 = c * CHUNK + nt * 64;
#pragma unroll
        for (int l = 0; l < 16; l++) {
            int lin = l * 256 + tid;
            int d = lin >> 6, j = lin & 63;
            Kt[j][d] = __expf(K[(size_t)d * HW + n0 + j] - rm[d]);
            Vt[j][d] = V[(size_t)d * HW + n0 + j];
        }
        __syncthreads();
#pragma unroll 4
        for (int j = 0; j < 64; j++) {
            float4 kf = *(const float4*)(&Kt[j][ty * 4]);
            u64 k0 = pack_dup(kf.x), k1 = pack_dup(kf.y);
            u64 k2 = pack_dup(kf.z), k3 = pack_dup(kf.w);
            ulonglong2 vv = *(const ulonglong2*)(&Vt[j][tx * 4]);
            ffma2(acc[0][0], k0, vv.x); ffma2(acc[0][1], k0, vv.y);
            ffma2(acc[1][0], k1, vv.x); ffma2(acc[1][1], k1, vv.y);
            ffma2(acc[2][0], k2, vv.x); ffma2(acc[2][1], k2, vv.y);
            ffma2(acc[3][0], k3, vv.x); ffma2(acc[3][1], k3, vv.y);
        }
        __syncthreads();
    }

    float* pb = part + ((size_t)c * BATCH * NH + b * NH + h) * (HD * HD);
#pragma unroll
    for (int i = 0; i < 4; i++) {
        float2 a = unpack2(acc[i][0]);
        float2 bb = unpack2(acc[i][1]);
        *(float4*)(&pb[(ty * 4 + i) * HD + tx * 4]) = make_float4(a.x, a.y, bb.x, bb.y);
    }
}

// ---------------------------------------------------------------------------
// Kernel 3c: reduce partials + mem-kv tail + rinv scaling -> ctx
// ---------------------------------------------------------------------------
__global__ __launch_bounds__(256) void ctxreduce_kernel(const float* __restrict__ part,
                                                        const float* __restrict__ memkv,
                                                        const float* __restrict__ rmax,
                                                        const float* __restrict__ rinv,
                                                        float* __restrict__ ctx) {
    int h = blockIdx.x, b = blockIdx.y;
    __shared__ float mkx[64][4];
    __shared__ float mvs[64][4];
    __shared__ float riv[64];
    int tid = threadIdx.x;
    if (tid < 64) riv[tid] = rinv[(b * NH + h) * HD + tid];
    {
        int d = tid >> 2, j = tid & 3;
        mkx[d][j] = __expf(memkv[((size_t)h * HD + d) * NMEM + j] -
                           rmax[(b * NH + h) * HD + d]);
        mvs[d][j] = memkv[(size_t)NH * HD * NMEM + ((size_t)h * HD + d) * NMEM + j];
    }
    __syncthreads();
    size_t base = (size_t)(b * NH + h) * (HD * HD);
    for (int l = tid; l < HD * HD; l += 256) {
        int d = l >> 6, e = l & 63;
        float s2 = 0.f;
#pragma unroll
        for (int cc = 0; cc < NC; cc++)
            s2 += part[(size_t)cc * BATCH * NH * HD * HD + base + l];
#pragma unroll
        for (int j = 0; j < 4; j++) s2 += mkx[d][j] * mvs[e][j];
        ctx[base + l] = s2 * riv[d];
    }
}

// ---------------------------------------------------------------------------
// Kernel 4: q-softmax + out[e][p] = sum_d ctx[d][e]*qs[d][p]; writes bf16
// splits TRANSPOSED [b][pos][hid] for the tensorized outnorm.
// ---------------------------------------------------------------------------
__global__ __launch_bounds__(256) void attend_kernel(const float* __restrict__ qkv,
                                                     const float* __restrict__ ctx,
                                                     __nv_bfloat16* __restrict__ a1,
                                                     __nv_bfloat16* __restrict__ a2) {
    int pos0 = blockIdx.x * 64;
    int h = blockIdx.y, b = blockIdx.z;
    const float* Q = qkv + ((size_t)b * O3 + h * HD) * HW;
    const float* cb = ctx + (size_t)(b * NH + h) * HD * HD;

    __shared__ __align__(16) float cs[64][68];
    __shared__ __align__(16) float qs[64][68];

    int tid = threadIdx.x;
    for (int l = tid; l < HD * HD; l += 256) {
        int d = l >> 6, e = l & 63;
        cs[d][e] = cb[l];
        qs[d][e] = Q[(size_t)d * HW + pos0 + e];
    }
    __syncthreads();

    if (tid < 64) {
        float m = -1e30f;
#pragma unroll
        for (int d = 0; d < HD; d++) m = fmaxf(m, qs[d][tid]);
        float ss = 0.f;
#pragma unroll
        for (int d = 0; d < HD; d++) ss += __expf(qs[d][tid] - m);
        float inv = 0.125f / ss;
#pragma unroll
        for (int d = 0; d < HD; d++)
            qs[d][tid] = __expf(qs[d][tid] - m) * inv;
    }
    __syncthreads();

    int tx = tid & 15, ty = tid >> 4;
    u64 acc[4][2];
#pragma unroll
    for (int i = 0; i < 4; i++) { acc[i][0] = 0ULL; acc[i][1] = 0ULL; }

#pragma unroll 4
    for (int d = 0; d < HD; d++) {
        float4 cf = *(const float4*)(&cs[d][ty * 4]);
        u64 c0 = pack_dup(cf.x), c1 = pack_dup(cf.y);
        u64 c2 = pack_dup(cf.z), c3 = pack_dup(cf.w);
        ulonglong2 qq = *(const ulonglong2*)(&qs[d][tx * 4]);
        ffma2(acc[0][0], c0, qq.x); ffma2(acc[0][1], c0, qq.y);
        ffma2(acc[1][0], c1, qq.x); ffma2(acc[1][1], c1, qq.y);
        ffma2(acc[2][0], c2, qq.x); ffma2(acc[2][1], c2, qq.y);
        ffma2(acc[3][0], c3, qq.x); ffma2(acc[3][1], c3, qq.y);
    }

    // Stage transposed result into cs as os[pos][e]
    __syncthreads();
#pragma unroll
    for (int i = 0; i < 4; i++) {
        float2 a = unpack2(acc[i][0]);
        float2 bb = unpack2(acc[i][1]);
        int e = ty * 4 + i;
        cs[tx * 4 + 0][e] = a.x;
        cs[tx * 4 + 1][e] = a.y;
        cs[tx * 4 + 2][e] = bb.x;
        cs[tx * 4 + 3][e] = bb.y;
    }
    __syncthreads();

    // Write bf16 splits: thread -> (pos = tid>>2, 16 e-values at (tid&3)*16)
    {
        int pos = tid >> 2, e0 = (tid & 3) * 16;
        size_t base = ((size_t)b * HW + pos0 + pos) * HID + h * HD + e0;
        uint32_t r1[8], r2[8];
#pragma unroll
        for (int u = 0; u < 8; u++) {
            float v0 = cs[pos][e0 + 2 * u], v1 = cs[pos][e0 + 2 * u + 1];
            __nv_bfloat16 h0 = __float2bfloat16_rn(v0);
            __nv_bfloat16 h1 = __float2bfloat16_rn(v1);
            r1[u] = pkbf(v0, v1);
            r2[u] = pkbf(v0 - __bfloat162float(h0), v1 - __bfloat162float(h1));
        }
        *(uint4*)((char*)a1 + base * 2)      = make_uint4(r1[0], r1[1], r1[2], r1[3]);
        *(uint4*)((char*)a1 + base * 2 + 16) = make_uint4(r1[4], r1[5], r1[6], r1[7]);
        *(uint4*)((char*)a2 + base * 2)      = make_uint4(r2[0], r2[1], r2[2], r2[3]);
        *(uint4*)((char*)a2 + base * 2 + 16) = make_uint4(r2[4], r2[5], r2[6], r2[7]);
    }
}

// ---------------------------------------------------------------------------
// Kernel 5: out GEMM via mma.sync bf16 split + bias + fused rmsnorm.
// CTA: M=256 (all channels) x N=64 (positions), K=512. 8 warps (4m x 2n),
// warp tile 64x32. cp.async double-buffered, K-tile 64.
// ---------------------------------------------------------------------------
#define OA_T   (256 * LDK * 2)        // 36864 per A split
#define OB_T   (64 * LDK * 2)         // 9216 per B split
#define OSTAGE (2 * OA_T + 2 * OB_T)  // 92160
#define OSMTOT (2 * OSTAGE)           // 184320
#define O_A1   0
#define O_A2   OA_T
#define O_B1   (2 * OA_T)
#define O_B2   (2 * OA_T + OB_T)

__global__ void __launch_bounds__(256)
outnorm_mma_kernel(const __nv_bfloat16* __restrict__ wo1,
                   const __nv_bfloat16* __restrict__ wo2,
                   const __nv_bfloat16* __restrict__ a1,
                   const __nv_bfloat16* __restrict__ a2,
                   const float* __restrict__ bias,
                   const float* __restrict__ gout,
                   float* __restrict__ out) {
    extern __shared__ char smem[];
    uint32_t sb = smem_u32(smem);
    __shared__ float colsq[64];
    __shared__ float invs[64];

    int tid = threadIdx.x;
    int warp = tid >> 5, lane = tid & 31;
    int b = blockIdx.y;
    int pos0 = blockIdx.x * 64;

    const char* srcA1 = (const char*)wo1;
    const char* srcA2 = (const char*)wo2;
    const char* srcB1 = (const char*)(a1 + ((size_t)b * HW + pos0) * HID);
    const char* srcB2 = (const char*)(a2 + ((size_t)b * HW + pos0) * HID);

    int lrow = tid >> 3, lseg = tid & 7;

    auto load_stage = [&](int st, int k0) {
        uint32_t dbase = sb + st * OSTAGE;
        // A: 256 rows, 8 passes of 32 rows
#pragma unroll
        for (int j = 0; j < 8; j++) {
            int row = lrow + j * 32;
            uint32_t dp = dbase + row * (LDK * 2) + lseg * 16;
            const char* s1 = srcA1 + (size_t)row * (HID * 2) + k0 * 2 + lseg * 16;
            const char* s2 = srcA2 + (size_t)row * (HID * 2) + k0 * 2 + lseg * 16;
            cp16(dp + O_A1, s1);
            cp16(dp + O_A2, s2);
        }
        // B: 64 rows, 2 passes of 32 rows
#pragma unroll
        for (int j = 0; j < 2; j++) {
            int row = lrow + j * 32;
            uint32_t dp = dbase + row * (LDK * 2) + lseg * 16;
            const char* s1 = srcB1 + (size_t)row * (HID * 2) + k0 * 2 + lseg * 16;
            const char* s2 = srcB2 + (size_t)row * (HID * 2) + k0 * 2 + lseg * 16;
            cp16(dp + O_B1, s1);
            cp16(dp + O_B2, s2);
        }
    };

    int mwarp = (warp >> 1) * 64;
    int nwarp = (warp & 1) * 32;

    float acc[4][4][4];
#pragma unroll
    for (int mi = 0; mi < 4; mi++)
#pragma unroll
        for (int nf = 0; nf < 4; nf++)
#pragma unroll
            for (int q = 0; q < 4; q++) acc[mi][nf][q] = 0.f;

    int flrow = lane & 7, mat = lane >> 3;
    int frow = (mat & 1) * 8 + flrow;
    int fk   = (mat >> 1) * 8;

    if (tid < 64) colsq[tid] = 0.f;

    load_stage(0, 0);
    CP_COMMIT();

    for (int kt = 0; kt < 8; kt++) {
        if (kt < 7) {
            load_stage((kt + 1) & 1, (kt + 1) * 64);
            CP_COMMIT();
            CP_WAIT1();
        } else {
            CP_WAIT0();
        }
        __syncthreads();
        uint32_t stb = sb + (kt & 1) * OSTAGE;

#pragma unroll
        for (int ks = 0; ks < 4; ks++) {
            int kk = ks * 16 + fk;
            uint32_t av1[4][4], av2[4][4];
#pragma unroll
            for (int mi = 0; mi < 4; mi++) {
                uint32_t off = (uint32_t)((mwarp + mi * 16 + frow) * (LDK * 2) + kk * 2);
                ldm4(av1[mi], stb + O_A1 + off);
                ldm4(av2[mi], stb + O_A2 + off);
            }
            uint32_t bv1[2][4], bv2[2][4];
#pragma unroll
            for (int nb = 0; nb < 2; nb++) {
                uint32_t off = (uint32_t)((nwarp + nb * 16 + frow) * (LDK * 2) + kk * 2);
                ldm4(bv1[nb], stb + O_B1 + off);
                ldm4(bv2[nb], stb + O_B2 + off);
            }
#pragma unroll
            for (int mi = 0; mi < 4; mi++)
#pragma unroll
                for (int nf = 0; nf < 4; nf++) {
                    int nb = nf >> 1, hi = nf & 1;
                    mma_bf16(acc[mi][nf], av1[mi], bv1[nb][hi], bv1[nb][hi + 2]);
                    mma_bf16(acc[mi][nf], av1[mi], bv2[nb][hi], bv2[nb][hi + 2]);
                    mma_bf16(acc[mi][nf], av2[mi], bv1[nb][hi], bv1[nb][hi + 2]);
                }
        }
        __syncthreads();
    }

    // bias + column sum-of-squares
    float cs0[4], cs1[4];
#pragma unroll
    for (int nf = 0; nf < 4; nf++) { cs0[nf] = 0.f; cs1[nf] = 0.f; }
#pragma unroll
    for (int mi = 0; mi < 4; mi++) {
        int row = mwarp + mi * 16 + (lane >> 2);
        float bi0 = bias[row], bi1 = bias[row + 8];
#pragma unroll
        for (int nf = 0; nf < 4; nf++) {
            acc[mi][nf][0] += bi0;
            acc[mi][nf][1] += bi0;
            acc[mi][nf][2] += bi1;
            acc[mi][nf][3] += bi1;
            cs0[nf] += acc[mi][nf][0] * acc[mi][nf][0] + acc[mi][nf][2] * acc[mi][nf][2];
            cs1[nf] += acc[mi][nf][1] * acc[mi][nf][1] + acc[mi][nf][3] * acc[mi][nf][3];
        }
    }
    // reduce over lanes sharing a column (lane>>2 varies)
#pragma unroll
    for (int nf = 0; nf < 4; nf++) {
#pragma unroll
        for (int o = 4; o < 32; o <<= 1) {
            cs0[nf] += __shfl_xor_sync(0xFFFFFFFFu, cs0[nf], o);
            cs1[nf] += __shfl_xor_sync(0xFFFFFFFFu, cs1[nf], o);
        }
    }
    if (lane < 4) {
#pragma unroll
        for (int nf = 0; nf < 4; nf++) {
            int col = nwarp + nf * 8 + lane * 2;
            atomicAdd(&colsq[col], cs0[nf]);
            atomicAdd(&colsq[col + 1], cs1[nf]);
        }
    }
    __syncthreads();
    if (tid < 64) invs[tid] = 16.0f / fmaxf(sqrtf(colsq[tid]), 1e-12f);
    __syncthreads();

    float* ob = out + (size_t)b * CIN * HW + pos0;
#pragma unroll
    for (int mi = 0; mi < 4; mi++) {
        int row = mwarp + mi * 16 + (lane >> 2);
        float gr0 = gout[row], gr1 = gout[row + 8];
#pragma unroll
        for (int nf = 0; nf < 4; nf++) {
            int col = nwarp + nf * 8 + (lane & 3) * 2;
            float i0 = invs[col], i1 = invs[col + 1];
            *(float2*)(ob + (size_t)row * HW + col) =
                make_float2(acc[mi][nf][0] * i0 * gr0, acc[mi][nf][1] * i1 * gr0);
            *(float2*)(ob + (size_t)(row + 8) * HW + col) =
                make_float2(acc[mi][nf][2] * i0 * gr1, acc[mi][nf][3] * i1 * gr1);
        }
    }
}

// ---------------------------------------------------------------------------
extern "C" void kernel_launch(void* const* d_in, const int* in_sizes, int n_in,
                              void* d_out, int out_size) {
    const float* x      = (const float*)d_in[0];
    const float* g_in   = (const float*)d_in[1];
    const float* w_qkv  = (const float*)d_in[2];
    const float* mem_kv = (const float*)d_in[3];
    const float* w_out  = (const float*)d_in[4];
    const float* b_out  = (const float*)d_in[5];
    const float* g_out  = (const float*)d_in[6];
    float* out = (float*)d_out;

    float *s_ptr, *qkv_ptr, *rmax_ptr, *rinv_ptr, *part_ptr, *ctx_ptr;
    __nv_bfloat16 *w1_ptr, *w2_ptr, *wo1_ptr, *wo2_ptr, *x1_ptr, *x2_ptr, *a1_ptr, *a2_ptr;
    cudaGetSymbolAddress((void**)&s_ptr,    g_s);
    cudaGetSymbolAddress((void**)&w1_ptr,   g_w1);
    cudaGetSymbolAddress((void**)&w2_ptr,   g_w2);
    cudaGetSymbolAddress((void**)&wo1_ptr,  g_wo1);
    cudaGetSymbolAddress((void**)&wo2_ptr,  g_wo2);
    cudaGetSymbolAddress((void**)&x1_ptr,   g_x1);
    cudaGetSymbolAddress((void**)&x2_ptr,   g_x2);
    cudaGetSymbolAddress((void**)&qkv_ptr,  g_qkv);
    cudaGetSymbolAddress((void**)&rmax_ptr, g_rmax);
    cudaGetSymbolAddress((void**)&rinv_ptr, g_rinv);
    cudaGetSymbolAddress((void**)&part_ptr, g_part);
    cudaGetSymbolAddress((void**)&ctx_ptr,  g_ctx);
    cudaGetSymbolAddress((void**)&a1_ptr,   g_a1);
    cudaGetSymbolAddress((void**)&a2_ptr,   g_a2);

    cudaFuncSetAttribute(qkv_mma_kernel,
                         cudaFuncAttributeMaxDynamicSharedMemorySize, QSMTOT);
    cudaFuncSetAttribute(outnorm_mma_kernel,
                         cudaFuncAttributeMaxDynamicSharedMemorySize, OSMTOT);

    colscale_kernel<<<(BATCH * HW + 255) / 256, 256>>>(x, s_ptr);
    wconv_kernel<<<(O3 * CIN + 255) / 256, 256>>>(w_qkv, g_in, w1_ptr, w2_ptr);
    woconv_kernel<<<(CIN * HID + 255) / 256, 256>>>(w_out, wo1_ptr, wo2_ptr);
    xconv_kernel<<<dim3(HW / 32, CIN / 32, BATCH), 256>>>(x, s_ptr, x1_ptr, x2_ptr);
    qkv_mma_kernel<<<dim3(HW / 128, O3 / 128, BATCH), 256, QSMTOT>>>(
        w1_ptr, w2_ptr, x1_ptr, x2_ptr, qkv_ptr);
    kstats_kernel<<<dim3(HD, NH, BATCH), 256>>>(qkv_ptr, mem_kv, rmax_ptr, rinv_ptr);
    ctxpart_kernel<<<dim3(NC, NH, BATCH), 256>>>(qkv_ptr, rmax_ptr, part_ptr);
    ctxreduce_kernel<<<dim3(NH, BATCH), 256>>>(part_ptr, mem_kv, rmax_ptr, rinv_ptr, ctx_ptr);
    attend_kernel<<<dim3(HW / 64, NH, BATCH), 256>>>(qkv_ptr, ctx_ptr, a1_ptr, a2_ptr);
    outnorm_mma_kernel<<<dim3(HW / 64, BATCH), 256, OSMTOT>>>(
        wo1_ptr, wo2_ptr, a1_ptr, a2_ptr, b_out, g_out, out);
}

// round 6
// speedup vs baseline: 1.9747x; 1.0025x over previous
#include <cuda_runtime.h>
#include <cuda_bf16.h>
#include <math.h>
#include <stdint.h>
#include <string.h>

// Problem constants
#define BATCH 16
#define CIN   256
#define HW    4096
#define O3    1536
#define HID   512
#define NH    8
#define HD    64
#define NMEM  4
#define NC    8
#define CHUNK 512

typedef unsigned long long u64;

// Scratch (device globals — allocation-free rule)
__device__ float g_s[BATCH * HW];
__device__ __nv_bfloat16 g_w1[O3 * CIN];
__device__ __nv_bfloat16 g_w2[O3 * CIN];
__device__ __nv_bfloat16 g_wo1[CIN * HID];
__device__ __nv_bfloat16 g_wo2[CIN * HID];
__device__ __nv_bfloat16 g_x1[(size_t)BATCH * HW * CIN];   // transposed [b][n][c]
__device__ __nv_bfloat16 g_x2[(size_t)BATCH * HW * CIN];
__device__ float g_qkv[(size_t)BATCH * O3 * HW];           // 402 MB
__device__ float g_rmax[BATCH * NH * HD];
__device__ float g_rinv[BATCH * NH * HD];
__device__ float g_part[(size_t)NC * BATCH * NH * HD * HD];
__device__ float g_ctx[BATCH * NH * HD * HD];
__device__ __nv_bfloat16 g_a1[(size_t)BATCH * HW * HID];   // att^T split [b][pos][hid]
__device__ __nv_bfloat16 g_a2[(size_t)BATCH * HW * HID];

// ---- packed f32x2 helpers ------------------------------------------------
__device__ __forceinline__ u64 pack_dup(float v) {
    u64 r; asm("mov.b64 %0, {%1, %2};" : "=l"(r) : "f"(v), "f"(v)); return r;
}
__device__ __forceinline__ void ffma2(u64& d, u64 a, u64 b) {
    asm("fma.rn.f32x2 %0, %1, %2, %0;" : "+l"(d) : "l"(a), "l"(b));
}
__device__ __forceinline__ float2 unpack2(u64 v) {
    float2 f; asm("mov.b64 {%0, %1}, %2;" : "=f"(f.x), "=f"(f.y) : "l"(v)); return f;
}

// ---- mma.sync helpers ------------------------------------------------------
__device__ __forceinline__ uint32_t smem_u32(const void* p) {
    uint32_t a;
    asm("{ .reg .u64 t; cvta.to.shared.u64 t, %1; cvt.u32.u64 %0, t; }"
        : "=r"(a) : "l"(p));
    return a;
}
__device__ __forceinline__ void ldm4(uint32_t* r, uint32_t addr) {
    asm volatile("ldmatrix.sync.aligned.m8n8.x4.shared.b16 {%0,%1,%2,%3}, [%4];"
                 : "=r"(r[0]), "=r"(r[1]), "=r"(r[2]), "=r"(r[3]) : "r"(addr));
}
__device__ __forceinline__ void mma_bf16(float* c, const uint32_t* a,
                                         uint32_t b0, uint32_t b1) {
    asm volatile(
        "mma.sync.aligned.m16n8k16.row.col.f32.bf16.bf16.f32 "
        "{%0,%1,%2,%3}, {%4,%5,%6,%7}, {%8,%9}, {%0,%1,%2,%3};"
        : "+f"(c[0]), "+f"(c[1]), "+f"(c[2]), "+f"(c[3])
        : "r"(a[0]), "r"(a[1]), "r"(a[2]), "r"(a[3]), "r"(b0), "r"(b1));
}
__device__ __forceinline__ void cp16(uint32_t dst, const void* src) {
    asm volatile("cp.async.cg.shared.global [%0], [%1], 16;"
                 :: "r"(dst), "l"(src));
}
#define CP_COMMIT() asm volatile("cp.async.commit_group;" ::: "memory")
#define CP_WAIT1()  asm volatile("cp.async.wait_group 1;" ::: "memory")
#define CP_WAIT0()  asm volatile("cp.async.wait_group 0;" ::: "memory")

__device__ __forceinline__ uint32_t pkbf(float lo, float hi) {
    __nv_bfloat162 t = __floats2bfloat162_rn(lo, hi);
    uint32_t r; memcpy(&r, &t, 4); return r;
}

// ---------------------------------------------------------------------------
// Kernel 1: per-position rmsnorm scale
// ---------------------------------------------------------------------------
__global__ __launch_bounds__(256) void colscale_kernel(const float* __restrict__ x,
                                                       float* __restrict__ s) {
    int idx = blockIdx.x * 256 + threadIdx.x;
    if (idx >= BATCH * HW) return;
    int b = idx >> 12, pos = idx & (HW - 1);
    const float* p = x + (size_t)b * CIN * HW + pos;
    float acc = 0.f;
#pragma unroll 8
    for (int c = 0; c < CIN; c++) {
        float v = p[(size_t)c * HW];
        acc += v * v;
    }
    s[idx] = 16.0f / fmaxf(sqrtf(acc), 1e-12f);
}

// ---------------------------------------------------------------------------
// Kernel 1b: W fold + bf16 2-way split
// ---------------------------------------------------------------------------
__global__ __launch_bounds__(256) void wconv_kernel(const float* __restrict__ w,
                                                    const float* __restrict__ g,
                                                    __nv_bfloat16* __restrict__ w1,
                                                    __nv_bfloat16* __restrict__ w2) {
    int i = blockIdx.x * 256 + threadIdx.x;
    if (i >= O3 * CIN) return;
    float wg = w[i] * g[i & (CIN - 1)];
    __nv_bfloat16 h = __float2bfloat16_rn(wg);
    w1[i] = h;
    w2[i] = __float2bfloat16_rn(wg - __bfloat162float(h));
}

// Kernel 1b2: w_out bf16 2-way split
__global__ __launch_bounds__(256) void woconv_kernel(const float* __restrict__ w,
                                                     __nv_bfloat16* __restrict__ w1,
                                                     __nv_bfloat16* __restrict__ w2) {
    int i = blockIdx.x * 256 + threadIdx.x;
    if (i >= CIN * HID) return;
    float v = w[i];
    __nv_bfloat16 h = __float2bfloat16_rn(v);
    w1[i] = h;
    w2[i] = __float2bfloat16_rn(v - __bfloat162float(h));
}

// ---------------------------------------------------------------------------
// Kernel 1c: X transpose to [b][n][c], fold rmsnorm scale, bf16 2-way split
// ---------------------------------------------------------------------------
__global__ __launch_bounds__(256) void xconv_kernel(const float* __restrict__ x,
                                                    const float* __restrict__ s,
                                                    __nv_bfloat16* __restrict__ x1,
                                                    __nv_bfloat16* __restrict__ x2) {
    int b = blockIdx.z;
    int c0 = blockIdx.y * 32, n0 = blockIdx.x * 32;
    __shared__ float t[32][33];
    int tid = threadIdx.x;
    int tx = tid & 31, ty = tid >> 5;
#pragma unroll
    for (int i = 0; i < 4; i++) {
        int c = ty + i * 8;
        t[c][tx] = x[((size_t)b * CIN + c0 + c) * HW + n0 + tx];
    }
    __syncthreads();
#pragma unroll
    for (int i = 0; i < 4; i++) {
        int nr = ty + i * 8;
        float sv = s[b * HW + n0 + nr];
        float v = t[tx][nr] * sv;
        __nv_bfloat16 h = __float2bfloat16_rn(v);
        size_t o = ((size_t)b * HW + n0 + nr) * CIN + c0 + tx;
        x1[o] = h;
        x2[o] = __float2bfloat16_rn(v - __bfloat162float(h));
    }
}

// ---------------------------------------------------------------------------
// Kernel 2: QKV GEMM via mma.sync bf16 split, cp.async double-buffered.
// CTA tile 128x128, K-tile 64, 2 stages, 512 threads / 16 warps (4m x 4n),
// warp tile 32x32.
// ---------------------------------------------------------------------------
#define LDK    72
#define TILEB  (128 * LDK * 2)        // 18432
#define STAGEB (4 * TILEB)            // 73728
#define QSMTOT (2 * STAGEB)           // 147456
#define OFF_A1 0
#define OFF_A2 TILEB
#define OFF_B1 (2 * TILEB)
#define OFF_B2 (3 * TILEB)

__global__ void __launch_bounds__(512)
qkv_mma_kernel(const __nv_bfloat16* __restrict__ w1,
               const __nv_bfloat16* __restrict__ w2,
               const __nv_bfloat16* __restrict__ x1,
               const __nv_bfloat16* __restrict__ x2,
               float* __restrict__ out) {
    extern __shared__ char smem[];
    uint32_t sb = smem_u32(smem);
    int tid = threadIdx.x;
    int warp = tid >> 5, lane = tid & 31;
    int b = blockIdx.z;
    int rowBase = blockIdx.y * 128;
    int colBase = blockIdx.x * 128;

    const char* src[4] = {
        (const char*)(w1 + (size_t)rowBase * CIN),
        (const char*)(w2 + (size_t)rowBase * CIN),
        (const char*)(x1 + ((size_t)b * HW + colBase) * CIN),
        (const char*)(x2 + ((size_t)b * HW + colBase) * CIN)};

    int lrow = tid >> 3, lseg = tid & 7;  // 64 rows x 8 segs per 512-thr pass

    auto load_stage = [&](int st, int k0) {
        uint32_t dbase = sb + st * STAGEB;
#pragma unroll
        for (int t4 = 0; t4 < 4; t4++) {
            const char* sp = src[t4] + k0 * 2 + lseg * 16;
            uint32_t dp = dbase + t4 * TILEB + lrow * (LDK * 2) + lseg * 16;
#pragma unroll
            for (int j = 0; j < 2; j++)
                cp16(dp + j * 64 * (LDK * 2), sp + (size_t)(lrow + j * 64) * (CIN * 2));
        }
    };

    int mwarp = (warp >> 2) * 32;
    int nwarp = (warp & 3) * 32;

    float acc[2][4][4];
#pragma unroll
    for (int mi = 0; mi < 2; mi++)
#pragma unroll
        for (int nf = 0; nf < 4; nf++)
#pragma unroll
            for (int q = 0; q < 4; q++) acc[mi][nf][q] = 0.f;

    int flrow = lane & 7, mat = lane >> 3;
    int frow = (mat & 1) * 8 + flrow;
    int fk   = (mat >> 1) * 8;

    load_stage(0, 0);
    CP_COMMIT();

    for (int kt = 0; kt < 4; kt++) {
        if (kt < 3) {
            load_stage((kt + 1) & 1, (kt + 1) * 64);
            CP_COMMIT();
            CP_WAIT1();
        } else {
            CP_WAIT0();
        }
        __syncthreads();
        uint32_t stb = sb + (kt & 1) * STAGEB;

#pragma unroll
        for (int ks = 0; ks < 4; ks++) {
            int kk = ks * 16 + fk;
            uint32_t a1[2][4], a2[2][4];
#pragma unroll
            for (int mi = 0; mi < 2; mi++) {
                uint32_t off = (uint32_t)((mwarp + mi * 16 + frow) * (LDK * 2) + kk * 2);
                ldm4(a1[mi], stb + OFF_A1 + off);
                ldm4(a2[mi], stb + OFF_A2 + off);
            }
            uint32_t b1[2][4], b2[2][4];
#pragma unroll
            for (int nb = 0; nb < 2; nb++) {
                uint32_t off = (uint32_t)((nwarp + nb * 16 + frow) * (LDK * 2) + kk * 2);
                ldm4(b1[nb], stb + OFF_B1 + off);
                ldm4(b2[nb], stb + OFF_B2 + off);
            }
#pragma unroll
            for (int mi = 0; mi < 2; mi++)
#pragma unroll
                for (int nf = 0; nf < 4; nf++) {
                    int nb = nf >> 1, hi = nf & 1;
                    mma_bf16(acc[mi][nf], a1[mi], b1[nb][hi], b1[nb][hi + 2]);
                    mma_bf16(acc[mi][nf], a1[mi], b2[nb][hi], b2[nb][hi + 2]);
                    mma_bf16(acc[mi][nf], a2[mi], b1[nb][hi], b1[nb][hi + 2]);
                }
        }
        __syncthreads();
    }

    float* obase = out + (size_t)b * O3 * HW;
#pragma unroll
    for (int mi = 0; mi < 2; mi++) {
        int row = rowBase + mwarp + mi * 16 + (lane >> 2);
#pragma unroll
        for (int nf = 0; nf < 4; nf++) {
            int col = colBase + nwarp + nf * 8 + (lane & 3) * 2;
            *(float2*)(obase + (size_t)row * HW + col) =
                make_float2(acc[mi][nf][0], acc[mi][nf][1]);
            *(float2*)(obase + (size_t)(row + 8) * HW + col) =
                make_float2(acc[mi][nf][2], acc[mi][nf][3]);
        }
    }
}

// ---------------------------------------------------------------------------
// Kernel 3a: k-softmax stats per (b,h,d) row
// ---------------------------------------------------------------------------
__global__ __launch_bounds__(256) void kstats_kernel(const float* __restrict__ qkv,
                                                     const float* __restrict__ memkv,
                                                     float* __restrict__ rmax,
                                                     float* __restrict__ rinv) {
    int d = blockIdx.x, h = blockIdx.y, b = blockIdx.z;
    int tid = threadIdx.x;
    const float* kr = qkv + ((size_t)b * O3 + HID + h * HD + d) * HW;
    const float* MK = memkv + ((size_t)h * HD + d) * NMEM;

    float v[16];
#pragma unroll
    for (int i = 0; i < 16; i++) v[i] = kr[i * 256 + tid];
    float m = v[0];
#pragma unroll
    for (int i = 1; i < 16; i++) m = fmaxf(m, v[i]);
    if (tid < NMEM) m = fmaxf(m, MK[tid]);

    __shared__ float red[8];
#pragma unroll
    for (int o = 16; o; o >>= 1) m = fmaxf(m, __shfl_xor_sync(0xFFFFFFFFu, m, o));
    if ((tid & 31) == 0) red[tid >> 5] = m;
    __syncthreads();
    if (tid == 0) {
        float t = red[0];
#pragma unroll
        for (int i = 1; i < 8; i++) t = fmaxf(t, red[i]);
        red[0] = t;
    }
    __syncthreads();
    m = red[0];
    __syncthreads();

    float ss = 0.f;
#pragma unroll
    for (int i = 0; i < 16; i++) ss += __expf(v[i] - m);
    if (tid < NMEM) ss += __expf(MK[tid] - m);
#pragma unroll
    for (int o = 16; o; o >>= 1) ss += __shfl_xor_sync(0xFFFFFFFFu, ss, o);
    if ((tid & 31) == 0) red[tid >> 5] = ss;
    __syncthreads();
    if (tid == 0) {
        float t = 0.f;
#pragma unroll
        for (int i = 0; i < 8; i++) t += red[i];
        int idx = (b * NH + h) * HD + d;
        rmax[idx] = m;
        rinv[idx] = 1.0f / t;
    }
}

// ---------------------------------------------------------------------------
// Kernel 3b: partial context over n chunks
// ---------------------------------------------------------------------------
__global__ __launch_bounds__(256) void ctxpart_kernel(const float* __restrict__ qkv,
                                                      const float* __restrict__ rmax,
                                                      float* __restrict__ part) {
    int c = blockIdx.x, h = blockIdx.y, b = blockIdx.z;
    const float* K = qkv + ((size_t)b * O3 + HID + h * HD) * HW;
    const float* V = qkv + ((size_t)b * O3 + 2 * HID + h * HD) * HW;

    __shared__ __align__(16) float Kt[64][68];
    __shared__ __align__(16) float Vt[64][68];
    __shared__ float rm[64];

    int tid = threadIdx.x;
    if (tid < 64) rm[tid] = rmax[(b * NH + h) * HD + tid];
    __syncthreads();

    int tx = tid & 15, ty = tid >> 4;
    u64 acc[4][2];
#pragma unroll
    for (int i = 0; i < 4; i++) { acc[i][0] = 0ULL; acc[i][1] = 0ULL; }

    for (int nt = 0; nt < CHUNK / 64; nt++) {
        int n0 = c * CHUNK + nt * 64;
#pragma unroll
        for (int l = 0; l < 16; l++) {
            int lin = l * 256 + tid;
            int d = lin >> 6, j = lin & 63;
            Kt[j][d] = __expf(K[(size_t)d * HW + n0 + j] - rm[d]);
            Vt[j][d] = V[(size_t)d * HW + n0 + j];
        }
        __syncthreads();
#pragma unroll 4
        for (int j = 0; j < 64; j++) {
            float4 kf = *(const float4*)(&Kt[j][ty * 4]);
            u64 k0 = pack_dup(kf.x), k1 = pack_dup(kf.y);
            u64 k2 = pack_dup(kf.z), k3 = pack_dup(kf.w);
            ulonglong2 vv = *(const ulonglong2*)(&Vt[j][tx * 4]);
            ffma2(acc[0][0], k0, vv.x); ffma2(acc[0][1], k0, vv.y);
            ffma2(acc[1][0], k1, vv.x); ffma2(acc[1][1], k1, vv.y);
            ffma2(acc[2][0], k2, vv.x); ffma2(acc[2][1], k2, vv.y);
            ffma2(acc[3][0], k3, vv.x); ffma2(acc[3][1], k3, vv.y);
        }
        __syncthreads();
    }

    float* pb = part + ((size_t)c * BATCH * NH + b * NH + h) * (HD * HD);
#pragma unroll
    for (int i = 0; i < 4; i++) {
        float2 a = unpack2(acc[i][0]);
        float2 bb = unpack2(acc[i][1]);
        *(float4*)(&pb[(ty * 4 + i) * HD + tx * 4]) = make_float4(a.x, a.y, bb.x, bb.y);
    }
}

// ---------------------------------------------------------------------------
// Kernel 3c: reduce partials + mem-kv tail + rinv scaling -> ctx
// ---------------------------------------------------------------------------
__global__ __launch_bounds__(256) void ctxreduce_kernel(const float* __restrict__ part,
                                                        const float* __restrict__ memkv,
                                                        const float* __restrict__ rmax,
                                                        const float* __restrict__ rinv,
                                                        float* __restrict__ ctx) {
    int h = blockIdx.x, b = blockIdx.y;
    __shared__ float mkx[64][4];
    __shared__ float mvs[64][4];
    __shared__ float riv[64];
    int tid = threadIdx.x;
    if (tid < 64) riv[tid] = rinv[(b * NH + h) * HD + tid];
    {
        int d = tid >> 2, j = tid & 3;
        mkx[d][j] = __expf(memkv[((size_t)h * HD + d) * NMEM + j] -
                           rmax[(b * NH + h) * HD + d]);
        mvs[d][j] = memkv[(size_t)NH * HD * NMEM + ((size_t)h * HD + d) * NMEM + j];
    }
    __syncthreads();
    size_t base = (size_t)(b * NH + h) * (HD * HD);
    for (int l = tid; l < HD * HD; l += 256) {
        int d = l >> 6, e = l & 63;
        float s2 = 0.f;
#pragma unroll
        for (int cc = 0; cc < NC; cc++)
            s2 += part[(size_t)cc * BATCH * NH * HD * HD + base + l];
#pragma unroll
        for (int j = 0; j < 4; j++) s2 += mkx[d][j] * mvs[e][j];
        ctx[base + l] = s2 * riv[d];
    }
}

// ---------------------------------------------------------------------------
// Kernel 4: q-softmax + out[e][p] = sum_d ctx[d][e]*qs[d][p]; writes bf16
// splits TRANSPOSED [b][pos][hid] for the tensorized outnorm.
// ---------------------------------------------------------------------------
__global__ __launch_bounds__(256) void attend_kernel(const float* __restrict__ qkv,
                                                     const float* __restrict__ ctx,
                                                     __nv_bfloat16* __restrict__ a1,
                                                     __nv_bfloat16* __restrict__ a2) {
    int pos0 = blockIdx.x * 64;
    int h = blockIdx.y, b = blockIdx.z;
    const float* Q = qkv + ((size_t)b * O3 + h * HD) * HW;
    const float* cb = ctx + (size_t)(b * NH + h) * HD * HD;

    __shared__ __align__(16) float cs[64][68];
    __shared__ __align__(16) float qs[64][68];

    int tid = threadIdx.x;
    for (int l = tid; l < HD * HD; l += 256) {
        int d = l >> 6, e = l & 63;
        cs[d][e] = cb[l];
        qs[d][e] = Q[(size_t)d * HW + pos0 + e];
    }
    __syncthreads();

    if (tid < 64) {
        float m = -1e30f;
#pragma unroll
        for (int d = 0; d < HD; d++) m = fmaxf(m, qs[d][tid]);
        float ss = 0.f;
#pragma unroll
        for (int d = 0; d < HD; d++) ss += __expf(qs[d][tid] - m);
        float inv = 0.125f / ss;
#pragma unroll
        for (int d = 0; d < HD; d++)
            qs[d][tid] = __expf(qs[d][tid] - m) * inv;
    }
    __syncthreads();

    int tx = tid & 15, ty = tid >> 4;
    u64 acc[4][2];
#pragma unroll
    for (int i = 0; i < 4; i++) { acc[i][0] = 0ULL; acc[i][1] = 0ULL; }

#pragma unroll 4
    for (int d = 0; d < HD; d++) {
        float4 cf = *(const float4*)(&cs[d][ty * 4]);
        u64 c0 = pack_dup(cf.x), c1 = pack_dup(cf.y);
        u64 c2 = pack_dup(cf.z), c3 = pack_dup(cf.w);
        ulonglong2 qq = *(const ulonglong2*)(&qs[d][tx * 4]);
        ffma2(acc[0][0], c0, qq.x); ffma2(acc[0][1], c0, qq.y);
        ffma2(acc[1][0], c1, qq.x); ffma2(acc[1][1], c1, qq.y);
        ffma2(acc[2][0], c2, qq.x); ffma2(acc[2][1], c2, qq.y);
        ffma2(acc[3][0], c3, qq.x); ffma2(acc[3][1], c3, qq.y);
    }

    // Stage transposed result into cs as os[pos][e]
    __syncthreads();
#pragma unroll
    for (int i = 0; i < 4; i++) {
        float2 a = unpack2(acc[i][0]);
        float2 bb = unpack2(acc[i][1]);
        int e = ty * 4 + i;
        cs[tx * 4 + 0][e] = a.x;
        cs[tx * 4 + 1][e] = a.y;
        cs[tx * 4 + 2][e] = bb.x;
        cs[tx * 4 + 3][e] = bb.y;
    }
    __syncthreads();

    // Write bf16 splits: thread -> (pos = tid>>2, 16 e-values at (tid&3)*16)
    {
        int pos = tid >> 2, e0 = (tid & 3) * 16;
        size_t base = ((size_t)b * HW + pos0 + pos) * HID + h * HD + e0;
        uint32_t r1[8], r2[8];
#pragma unroll
        for (int u = 0; u < 8; u++) {
            float v0 = cs[pos][e0 + 2 * u], v1 = cs[pos][e0 + 2 * u + 1];
            __nv_bfloat16 h0 = __float2bfloat16_rn(v0);
            __nv_bfloat16 h1 = __float2bfloat16_rn(v1);
            r1[u] = pkbf(v0, v1);
            r2[u] = pkbf(v0 - __bfloat162float(h0), v1 - __bfloat162float(h1));
        }
        *(uint4*)((char*)a1 + base * 2)      = make_uint4(r1[0], r1[1], r1[2], r1[3]);
        *(uint4*)((char*)a1 + base * 2 + 16) = make_uint4(r1[4], r1[5], r1[6], r1[7]);
        *(uint4*)((char*)a2 + base * 2)      = make_uint4(r2[0], r2[1], r2[2], r2[3]);
        *(uint4*)((char*)a2 + base * 2 + 16) = make_uint4(r2[4], r2[5], r2[6], r2[7]);
    }
}

// ---------------------------------------------------------------------------
// Kernel 5: out GEMM via mma.sync bf16 split + bias + fused rmsnorm.
// CTA: M=256 x N=64, K=512, 512 threads / 16 warps (8m x 2n), warp tile
// 32x32. cp.async double-buffered, K-tile 64.
// ---------------------------------------------------------------------------
#define OA_T   (256 * LDK * 2)        // 36864 per A split
#define OB_T   (64 * LDK * 2)         // 9216 per B split
#define OSTAGE (2 * OA_T + 2 * OB_T)  // 92160
#define OSMTOT (2 * OSTAGE)           // 184320
#define O_A1   0
#define O_A2   OA_T
#define O_B1   (2 * OA_T)
#define O_B2   (2 * OA_T + OB_T)

__global__ void __launch_bounds__(512)
outnorm_mma_kernel(const __nv_bfloat16* __restrict__ wo1,
                   const __nv_bfloat16* __restrict__ wo2,
                   const __nv_bfloat16* __restrict__ a1,
                   const __nv_bfloat16* __restrict__ a2,
                   const float* __restrict__ bias,
                   const float* __restrict__ gout,
                   float* __restrict__ out) {
    extern __shared__ char smem[];
    uint32_t sb = smem_u32(smem);
    __shared__ float colsq[64];
    __shared__ float invs[64];

    int tid = threadIdx.x;
    int warp = tid >> 5, lane = tid & 31;
    int b = blockIdx.y;
    int pos0 = blockIdx.x * 64;

    const char* srcA1 = (const char*)wo1;
    const char* srcA2 = (const char*)wo2;
    const char* srcB1 = (const char*)(a1 + ((size_t)b * HW + pos0) * HID);
    const char* srcB2 = (const char*)(a2 + ((size_t)b * HW + pos0) * HID);

    int lrow = tid >> 3, lseg = tid & 7;   // 64 rows per pass with 512 threads

    auto load_stage = [&](int st, int k0) {
        uint32_t dbase = sb + st * OSTAGE;
        // A: 256 rows, 4 passes of 64 rows
#pragma unroll
        for (int j = 0; j < 4; j++) {
            int row = lrow + j * 64;
            uint32_t dp = dbase + row * (LDK * 2) + lseg * 16;
            const char* s1 = srcA1 + (size_t)row * (HID * 2) + k0 * 2 + lseg * 16;
            const char* s2 = srcA2 + (size_t)row * (HID * 2) + k0 * 2 + lseg * 16;
            cp16(dp + O_A1, s1);
            cp16(dp + O_A2, s2);
        }
        // B: 64 rows, 1 pass
        {
            int row = lrow;
            uint32_t dp = dbase + row * (LDK * 2) + lseg * 16;
            const char* s1 = srcB1 + (size_t)row * (HID * 2) + k0 * 2 + lseg * 16;
            const char* s2 = srcB2 + (size_t)row * (HID * 2) + k0 * 2 + lseg * 16;
            cp16(dp + O_B1, s1);
            cp16(dp + O_B2, s2);
        }
    };

    int mwarp = (warp >> 1) * 32;
    int nwarp = (warp & 1) * 32;

    float acc[2][4][4];
#pragma unroll
    for (int mi = 0; mi < 2; mi++)
#pragma unroll
        for (int nf = 0; nf < 4; nf++)
#pragma unroll
            for (int q = 0; q < 4; q++) acc[mi][nf][q] = 0.f;

    int flrow = lane & 7, mat = lane >> 3;
    int frow = (mat & 1) * 8 + flrow;
    int fk   = (mat >> 1) * 8;

    if (tid < 64) colsq[tid] = 0.f;

    load_stage(0, 0);
    CP_COMMIT();

    for (int kt = 0; kt < 8; kt++) {
        if (kt < 7) {
            load_stage((kt + 1) & 1, (kt + 1) * 64);
            CP_COMMIT();
            CP_WAIT1();
        } else {
            CP_WAIT0();
        }
        __syncthreads();
        uint32_t stb = sb + (kt & 1) * OSTAGE;

#pragma unroll
        for (int ks = 0; ks < 4; ks++) {
            int kk = ks * 16 + fk;
            uint32_t av1[2][4], av2[2][4];
#pragma unroll
            for (int mi = 0; mi < 2; mi++) {
                uint32_t off = (uint32_t)((mwarp + mi * 16 + frow) * (LDK * 2) + kk * 2);
                ldm4(av1[mi], stb + O_A1 + off);
                ldm4(av2[mi], stb + O_A2 + off);
            }
            uint32_t bv1[2][4], bv2[2][4];
#pragma unroll
            for (int nb = 0; nb < 2; nb++) {
                uint32_t off = (uint32_t)((nwarp + nb * 16 + frow) * (LDK * 2) + kk * 2);
                ldm4(bv1[nb], stb + O_B1 + off);
                ldm4(bv2[nb], stb + O_B2 + off);
            }
#pragma unroll
            for (int mi = 0; mi < 2; mi++)
#pragma unroll
                for (int nf = 0; nf < 4; nf++) {
                    int nb = nf >> 1, hi = nf & 1;
                    mma_bf16(acc[mi][nf], av1[mi], bv1[nb][hi], bv1[nb][hi + 2]);
                    mma_bf16(acc[mi][nf], av1[mi], bv2[nb][hi], bv2[nb][hi + 2]);
                    mma_bf16(acc[mi][nf], av2[mi], bv1[nb][hi], bv1[nb][hi + 2]);
                }
        }
        __syncthreads();
    }

    // bias + column sum-of-squares
    float cs0[4], cs1[4];
#pragma unroll
    for (int nf = 0; nf < 4; nf++) { cs0[nf] = 0.f; cs1[nf] = 0.f; }
#pragma unroll
    for (int mi = 0; mi < 2; mi++) {
        int row = mwarp + mi * 16 + (lane >> 2);
        float bi0 = bias[row], bi1 = bias[row + 8];
#pragma unroll
        for (int nf = 0; nf < 4; nf++) {
            acc[mi][nf][0] += bi0;
            acc[mi][nf][1] += bi0;
            acc[mi][nf][2] += bi1;
            acc[mi][nf][3] += bi1;
            cs0[nf] += acc[mi][nf][0] * acc[mi][nf][0] + acc[mi][nf][2] * acc[mi][nf][2];
            cs1[nf] += acc[mi][nf][1] * acc[mi][nf][1] + acc[mi][nf][3] * acc[mi][nf][3];
        }
    }
#pragma unroll
    for (int nf = 0; nf < 4; nf++) {
#pragma unroll
        for (int o = 4; o < 32; o <<= 1) {
            cs0[nf] += __shfl_xor_sync(0xFFFFFFFFu, cs0[nf], o);
            cs1[nf] += __shfl_xor_sync(0xFFFFFFFFu, cs1[nf], o);
        }
    }
    if (lane < 4) {
#pragma unroll
        for (int nf = 0; nf < 4; nf++) {
            int col = nwarp + nf * 8 + lane * 2;
            atomicAdd(&colsq[col], cs0[nf]);
            atomicAdd(&colsq[col + 1], cs1[nf]);
        }
    }
    __syncthreads();
    if (tid < 64) invs[tid] = 16.0f / fmaxf(sqrtf(colsq[tid]), 1e-12f);
    __syncthreads();

    float* ob = out + (size_t)b * CIN * HW + pos0;
#pragma unroll
    for (int mi = 0; mi < 2; mi++) {
        int row = mwarp + mi * 16 + (lane >> 2);
        float gr0 = gout[row], gr1 = gout[row + 8];
#pragma unroll
        for (int nf = 0; nf < 4; nf++) {
            int col = nwarp + nf * 8 + (lane & 3) * 2;
            float i0 = invs[col], i1 = invs[col + 1];
            *(float2*)(ob + (size_t)row * HW + col) =
                make_float2(acc[mi][nf][0] * i0 * gr0, acc[mi][nf][1] * i1 * gr0);
            *(float2*)(ob + (size_t)(row + 8) * HW + col) =
                make_float2(acc[mi][nf][2] * i0 * gr1, acc[mi][nf][3] * i1 * gr1);
        }
    }
}

// ---------------------------------------------------------------------------
extern "C" void kernel_launch(void* const* d_in, const int* in_sizes, int n_in,
                              void* d_out, int out_size) {
    const float* x      = (const float*)d_in[0];
    const float* g_in   = (const float*)d_in[1];
    const float* w_qkv  = (const float*)d_in[2];
    const float* mem_kv = (const float*)d_in[3];
    const float* w_out  = (const float*)d_in[4];
    const float* b_out  = (const float*)d_in[5];
    const float* g_out  = (const float*)d_in[6];
    float* out = (float*)d_out;

    float *s_ptr, *qkv_ptr, *rmax_ptr, *rinv_ptr, *part_ptr, *ctx_ptr;
    __nv_bfloat16 *w1_ptr, *w2_ptr, *wo1_ptr, *wo2_ptr, *x1_ptr, *x2_ptr, *a1_ptr, *a2_ptr;
    cudaGetSymbolAddress((void**)&s_ptr,    g_s);
    cudaGetSymbolAddress((void**)&w1_ptr,   g_w1);
    cudaGetSymbolAddress((void**)&w2_ptr,   g_w2);
    cudaGetSymbolAddress((void**)&wo1_ptr,  g_wo1);
    cudaGetSymbolAddress((void**)&wo2_ptr,  g_wo2);
    cudaGetSymbolAddress((void**)&x1_ptr,   g_x1);
    cudaGetSymbolAddress((void**)&x2_ptr,   g_x2);
    cudaGetSymbolAddress((void**)&qkv_ptr,  g_qkv);
    cudaGetSymbolAddress((void**)&rmax_ptr, g_rmax);
    cudaGetSymbolAddress((void**)&rinv_ptr, g_rinv);
    cudaGetSymbolAddress((void**)&part_ptr, g_part);
    cudaGetSymbolAddress((void**)&ctx_ptr,  g_ctx);
    cudaGetSymbolAddress((void**)&a1_ptr,   g_a1);
    cudaGetSymbolAddress((void**)&a2_ptr,   g_a2);

    cudaFuncSetAttribute(qkv_mma_kernel,
                         cudaFuncAttributeMaxDynamicSharedMemorySize, QSMTOT);
    cudaFuncSetAttribute(outnorm_mma_kernel,
                         cudaFuncAttributeMaxDynamicSharedMemorySize, OSMTOT);

    colscale_kernel<<<(BATCH * HW + 255) / 256, 256>>>(x, s_ptr);
    wconv_kernel<<<(O3 * CIN + 255) / 256, 256>>>(w_qkv, g_in, w1_ptr, w2_ptr);
    woconv_kernel<<<(CIN * HID + 255) / 256, 256>>>(w_out, wo1_ptr, wo2_ptr);
    xconv_kernel<<<dim3(HW / 32, CIN / 32, BATCH), 256>>>(x, s_ptr, x1_ptr, x2_ptr);
    qkv_mma_kernel<<<dim3(HW / 128, O3 / 128, BATCH), 512, QSMTOT>>>(
        w1_ptr, w2_ptr, x1_ptr, x2_ptr, qkv_ptr);
    kstats_kernel<<<dim3(HD, NH, BATCH), 256>>>(qkv_ptr, mem_kv, rmax_ptr, rinv_ptr);
    ctxpart_kernel<<<dim3(NC, NH, BATCH), 256>>>(qkv_ptr, rmax_ptr, part_ptr);
    ctxreduce_kernel<<<dim3(NH, BATCH), 256>>>(part_ptr, mem_kv, rmax_ptr, rinv_ptr, ctx_ptr);
    attend_kernel<<<dim3(HW / 64, NH, BATCH), 256>>>(qkv_ptr, ctx_ptr, a1_ptr, a2_ptr);
    outnorm_mma_kernel<<<dim3(HW / 64, BATCH), 512, OSMTOT>>>(
        wo1_ptr, wo2_ptr, a1_ptr, a2_ptr, b_out, g_out, out);
}